// round 1
// baseline (speedup 1.0000x reference)
#include <cuda_runtime.h>

// Problem constants (fixed shapes for this problem)
constexpr int IDIM = 384;
constexpr int JDIM = 384;
constexpr int NPIX = IDIM * JDIM;      // 147456
constexpr int CH   = 128;              // c_in
constexpr int NH   = 4;                // heads
constexpr int HD   = 32;               // head dim
constexpr float LN_EPS = 1e-5f;
constexpr float QSCALE = 0.17677669529663687f;  // 1/sqrt(32)

// Static device scratch (allocation-free rule: __device__ globals)
__device__ float g_xn[(size_t)NPIX * CH];        // layernormed x
__device__ float g_qkvg[(size_t)NPIX * 512];     // q|k|v|g concatenated per pixel
__device__ float g_tri[(size_t)NH * NPIX];       // triangle bias per head, (q,k) plane
__device__ float g_og[(size_t)NPIX * CH];        // gated attention output

// ---------------------------------------------------------------------------
// Kernel 1: LayerNorm over channels + triangle bias projection (C -> H)
// One warp per pixel. 8 warps per 256-thread block.
// ---------------------------------------------------------------------------
__global__ void ln_tri_kernel(const float* __restrict__ x,
                              const float* __restrict__ ln_w,
                              const float* __restrict__ ln_b,
                              const float* __restrict__ w_tri) {
    int gw   = (blockIdx.x * blockDim.x + threadIdx.x) >> 5;   // pixel index
    int lane = threadIdx.x & 31;
    if (gw >= NPIX) return;

    const float4 xv = ((const float4*)(x + (size_t)gw * CH))[lane];

    float s = xv.x + xv.y + xv.z + xv.w;
    #pragma unroll
    for (int o = 16; o; o >>= 1) s += __shfl_xor_sync(0xffffffffu, s, o);
    float mu = s * (1.0f / 128.0f);

    float dx0 = xv.x - mu, dx1 = xv.y - mu, dx2 = xv.z - mu, dx3 = xv.w - mu;
    float vv = dx0*dx0 + dx1*dx1 + dx2*dx2 + dx3*dx3;
    #pragma unroll
    for (int o = 16; o; o >>= 1) vv += __shfl_xor_sync(0xffffffffu, vv, o);
    float rs = rsqrtf(vv * (1.0f / 128.0f) + LN_EPS);

    float4 w = ((const float4*)ln_w)[lane];
    float4 b = ((const float4*)ln_b)[lane];
    float4 xn;
    xn.x = dx0 * rs * w.x + b.x;
    xn.y = dx1 * rs * w.y + b.y;
    xn.z = dx2 * rs * w.z + b.z;
    xn.w = dx3 * rs * w.w + b.w;
    ((float4*)(g_xn + (size_t)gw * CH))[lane] = xn;

    // tri[h] = sum_c xn[c] * w_tri[c][h]; w_tri is row-major [128][4]
    const float4* wt = (const float4*)w_tri;  // wt[c] = w_tri[c][0..3]
    float4 t0 = wt[lane * 4 + 0];
    float4 t1 = wt[lane * 4 + 1];
    float4 t2 = wt[lane * 4 + 2];
    float4 t3 = wt[lane * 4 + 3];
    float th0 = xn.x * t0.x + xn.y * t1.x + xn.z * t2.x + xn.w * t3.x;
    float th1 = xn.x * t0.y + xn.y * t1.y + xn.z * t2.y + xn.w * t3.y;
    float th2 = xn.x * t0.z + xn.y * t1.z + xn.z * t2.z + xn.w * t3.z;
    float th3 = xn.x * t0.w + xn.y * t1.w + xn.z * t2.w + xn.w * t3.w;
    #pragma unroll
    for (int o = 16; o; o >>= 1) {
        th0 += __shfl_xor_sync(0xffffffffu, th0, o);
        th1 += __shfl_xor_sync(0xffffffffu, th1, o);
        th2 += __shfl_xor_sync(0xffffffffu, th2, o);
        th3 += __shfl_xor_sync(0xffffffffu, th3, o);
    }
    if (lane == 0) {
        g_tri[0 * (size_t)NPIX + gw] = th0;
        g_tri[1 * (size_t)NPIX + gw] = th1;
        g_tri[2 * (size_t)NPIX + gw] = th2;
        g_tri[3 * (size_t)NPIX + gw] = th3;
    }
}

// ---------------------------------------------------------------------------
// Kernel 2: fp32 GEMM  C[M x 128] = A[M x 128] * B[128 x 128] (+ bias)
// mode 0..3: A = g_xn,  C = g_qkvg + mode*128 (ldc = 512)   [q,k,v,g proj]
// mode 4:    A = g_og,  C = Cext (d_out, ldc = 128)         [output proj]
// Tile 64x64, K in two chunks of 64, 4x4 register micro-tile, 256 threads.
// ---------------------------------------------------------------------------
__global__ void gemm_kernel(const float* __restrict__ B,
                            const float* __restrict__ bias,
                            float* __restrict__ Cext,
                            int mode) {
    __shared__ float As[64][68];   // padded: conflict-free column reads
    __shared__ float Bs[64][64];

    const float* A = (mode < 4) ? g_xn : g_og;
    float* Cp;
    int ldc;
    if (mode < 4) { Cp = g_qkvg + mode * 128; ldc = 512; }
    else          { Cp = Cext;                ldc = 128; }

    int bm  = blockIdx.x * 64;
    int bn  = blockIdx.y * 64;
    int tid = threadIdx.x;
    int tx  = tid & 15;   // column group
    int ty  = tid >> 4;   // row group

    float acc[4][4];
    #pragma unroll
    for (int r = 0; r < 4; ++r)
        #pragma unroll
        for (int c = 0; c < 4; ++c) acc[r][c] = 0.0f;

    for (int kc = 0; kc < 2; ++kc) {
        __syncthreads();
        #pragma unroll
        for (int l = 0; l < 4; ++l) {
            int idx = tid + l * 256;            // 64 rows * 16 float4 = 1024
            int r = idx >> 4, c4 = idx & 15;
            float4 av = *(const float4*)(A + (size_t)(bm + r) * 128 + kc * 64 + c4 * 4);
            As[r][c4 * 4 + 0] = av.x;
            As[r][c4 * 4 + 1] = av.y;
            As[r][c4 * 4 + 2] = av.z;
            As[r][c4 * 4 + 3] = av.w;
        }
        #pragma unroll
        for (int l = 0; l < 4; ++l) {
            int idx = tid + l * 256;
            int k = idx >> 4, c4 = idx & 15;
            *(float4*)&Bs[k][c4 * 4] =
                *(const float4*)(B + (size_t)(kc * 64 + k) * 128 + bn + c4 * 4);
        }
        __syncthreads();

        #pragma unroll
        for (int k = 0; k < 64; ++k) {
            float a0 = As[ty * 4 + 0][k];
            float a1 = As[ty * 4 + 1][k];
            float a2 = As[ty * 4 + 2][k];
            float a3 = As[ty * 4 + 3][k];
            float4 bv = *(const float4*)&Bs[k][tx * 4];
            acc[0][0] += a0 * bv.x; acc[0][1] += a0 * bv.y; acc[0][2] += a0 * bv.z; acc[0][3] += a0 * bv.w;
            acc[1][0] += a1 * bv.x; acc[1][1] += a1 * bv.y; acc[1][2] += a1 * bv.z; acc[1][3] += a1 * bv.w;
            acc[2][0] += a2 * bv.x; acc[2][1] += a2 * bv.y; acc[2][2] += a2 * bv.z; acc[2][3] += a2 * bv.w;
            acc[3][0] += a3 * bv.x; acc[3][1] += a3 * bv.y; acc[3][2] += a3 * bv.z; acc[3][3] += a3 * bv.w;
        }
    }

    float b0 = 0.f, b1 = 0.f, b2 = 0.f, b3 = 0.f;
    if (bias) {
        b0 = bias[bn + tx * 4 + 0];
        b1 = bias[bn + tx * 4 + 1];
        b2 = bias[bn + tx * 4 + 2];
        b3 = bias[bn + tx * 4 + 3];
    }
    #pragma unroll
    for (int r = 0; r < 4; ++r) {
        int row = bm + ty * 4 + r;
        float4 ov;
        ov.x = acc[r][0] + b0;
        ov.y = acc[r][1] + b1;
        ov.z = acc[r][2] + b2;
        ov.w = acc[r][3] + b3;
        *(float4*)(Cp + (size_t)row * ldc + bn + tx * 4) = ov;
    }
}

// ---------------------------------------------------------------------------
// Kernel 3: flash-style attention per (q-tile of 128, head, row i).
// 128 threads, one query row per thread. K/V tiles of 128 keys in smem
// (broadcast reads). Triangle+mask bias staged per 32-key chunk into
// XOR-swizzled smem. Chunked online softmax. Gating fused into epilogue.
// Static smem = 3 * 128*32*4 = 48 KB exactly.
// ---------------------------------------------------------------------------
__global__ void __launch_bounds__(128) attn_kernel(const float* __restrict__ mask) {
    __shared__ float Ksm[128][32];
    __shared__ float Vsm[128][32];
    __shared__ float Ts[128][32];   // XOR-swizzled bias tile

    int qt  = blockIdx.x;   // 0..2
    int h   = blockIdx.y;   // 0..3
    int i   = blockIdx.z;   // 0..383
    int tid = threadIdx.x;  // 0..127
    int q   = qt * 128 + tid;

    size_t prow = ((size_t)i * JDIM + q) * 512;

    float qreg[32];
    {
        const float4* qp = (const float4*)(g_qkvg + prow + h * HD);
        #pragma unroll
        for (int j = 0; j < 8; ++j) {
            float4 t = qp[j];
            qreg[4 * j + 0] = t.x * QSCALE;
            qreg[4 * j + 1] = t.y * QSCALE;
            qreg[4 * j + 2] = t.z * QSCALE;
            qreg[4 * j + 3] = t.w * QSCALE;
        }
    }

    float m = -1e30f, l = 0.0f;
    float o[32];
    #pragma unroll
    for (int d = 0; d < 32; ++d) o[d] = 0.0f;

    const float* trih = g_tri + (size_t)h * NPIX;   // [q][k] plane, stride 384
    const float* mrow = mask + (size_t)i * JDIM;
    int sw = tid & 31;

    for (int kt = 0; kt < 3; ++kt) {
        int k0 = kt * 128;
        __syncthreads();   // protect Ksm/Vsm reuse
        #pragma unroll
        for (int l2 = 0; l2 < 8; ++l2) {
            int idx = tid + l2 * 128;           // 128 rows * 8 float4
            int r = idx >> 3, c4 = idx & 7;
            size_t base = ((size_t)i * JDIM + k0 + r) * 512 + h * HD + c4 * 4;
            *(float4*)&Ksm[r][c4 * 4] = *(const float4*)(g_qkvg + base + 128);
            *(float4*)&Vsm[r][c4 * 4] = *(const float4*)(g_qkvg + base + 256);
        }

        for (int ks = 0; ks < 4; ++ks) {
            __syncthreads();   // Ts reuse + (first iter) K/V visibility
            // stage bias tile: tri[h][q0+r][kcol] + 1e9*(mask[i][kcol]-1)
            #pragma unroll
            for (int l2 = 0; l2 < 8; ++l2) {
                int idx = tid + l2 * 128;
                int r = idx >> 3, c4 = idx & 7;
                int kcol = k0 + ks * 32 + c4 * 4;
                float4 tv = *(const float4*)(trih + (size_t)(qt * 128 + r) * JDIM + kcol);
                float4 mv = *(const float4*)(mrow + kcol);
                int rsw = r & 31;
                Ts[r][(c4 * 4 + 0) ^ rsw] = tv.x + 1e9f * (mv.x - 1.0f);
                Ts[r][(c4 * 4 + 1) ^ rsw] = tv.y + 1e9f * (mv.y - 1.0f);
                Ts[r][(c4 * 4 + 2) ^ rsw] = tv.z + 1e9f * (mv.z - 1.0f);
                Ts[r][(c4 * 4 + 3) ^ rsw] = tv.w + 1e9f * (mv.w - 1.0f);
            }
            __syncthreads();

            float sv[32];
            #pragma unroll
            for (int kk = 0; kk < 32; ++kk) {
                int kr = ks * 32 + kk;
                float s = Ts[tid][kk ^ sw];
                #pragma unroll
                for (int d = 0; d < 32; d += 4) {
                    float4 kv = *(const float4*)&Ksm[kr][d];
                    s += qreg[d + 0] * kv.x + qreg[d + 1] * kv.y
                       + qreg[d + 2] * kv.z + qreg[d + 3] * kv.w;
                }
                sv[kk] = s;
            }

            float cm = sv[0];
            #pragma unroll
            for (int kk = 1; kk < 32; ++kk) cm = fmaxf(cm, sv[kk]);
            float mn = fmaxf(m, cm);
            float alpha = __expf(m - mn);
            m = mn;
            l *= alpha;
            #pragma unroll
            for (int d = 0; d < 32; ++d) o[d] *= alpha;

            #pragma unroll
            for (int kk = 0; kk < 32; ++kk) {
                int kr = ks * 32 + kk;
                float p = __expf(sv[kk] - mn);
                l += p;
                #pragma unroll
                for (int d = 0; d < 32; d += 4) {
                    float4 vv = *(const float4*)&Vsm[kr][d];
                    o[d + 0] += p * vv.x;
                    o[d + 1] += p * vv.y;
                    o[d + 2] += p * vv.z;
                    o[d + 3] += p * vv.w;
                }
            }
        }
    }

    float inv = 1.0f / l;
    float* op = g_og + ((size_t)i * JDIM + q) * CH + h * HD;
    const float4* gp = (const float4*)(g_qkvg + prow + 384 + h * HD);
    #pragma unroll
    for (int j = 0; j < 8; ++j) {
        float4 gv = gp[j];
        float4 ov;
        ov.x = o[4 * j + 0] * inv * (1.0f / (1.0f + __expf(-gv.x)));
        ov.y = o[4 * j + 1] * inv * (1.0f / (1.0f + __expf(-gv.y)));
        ov.z = o[4 * j + 2] * inv * (1.0f / (1.0f + __expf(-gv.z)));
        ov.w = o[4 * j + 3] * inv * (1.0f / (1.0f + __expf(-gv.w)));
        *(float4*)(op + 4 * j) = ov;
    }
}

// ---------------------------------------------------------------------------
// Launch
// Inputs (metadata order): x, mask, ln_w, ln_b, w_tri, wq, wk, wv, wg, bg, wo, bo
// ---------------------------------------------------------------------------
extern "C" void kernel_launch(void* const* d_in, const int* in_sizes, int n_in,
                              void* d_out, int out_size) {
    const float* x     = (const float*)d_in[0];
    const float* mask  = (const float*)d_in[1];
    const float* ln_w  = (const float*)d_in[2];
    const float* ln_b  = (const float*)d_in[3];
    const float* w_tri = (const float*)d_in[4];
    const float* wq    = (const float*)d_in[5];
    const float* wk    = (const float*)d_in[6];
    const float* wv    = (const float*)d_in[7];
    const float* wg    = (const float*)d_in[8];
    const float* bg    = (const float*)d_in[9];
    const float* wo    = (const float*)d_in[10];
    const float* bo    = (const float*)d_in[11];
    float* out = (float*)d_out;

    // 1) LayerNorm + triangle bias
    ln_tri_kernel<<<NPIX / 8, 256>>>(x, ln_w, ln_b, w_tri);

    // 2) Q/K/V/G projections
    dim3 gg(NPIX / 64, 2);
    gemm_kernel<<<gg, 256>>>(wq, nullptr, nullptr, 0);
    gemm_kernel<<<gg, 256>>>(wk, nullptr, nullptr, 1);
    gemm_kernel<<<gg, 256>>>(wv, nullptr, nullptr, 2);
    gemm_kernel<<<gg, 256>>>(wg, bg,      nullptr, 3);

    // 3) attention with triangle bias + mask bias + gating
    attn_kernel<<<dim3(3, NH, IDIM), 128>>>(mask);

    // 4) output projection + bias
    gemm_kernel<<<gg, 256>>>(wo, bo, out, 4);
}

// round 2
// speedup vs baseline: 1.7379x; 1.7379x over previous
#include <cuda_runtime.h>
#include <cstdint>

constexpr int IDIM = 384;
constexpr int JDIM = 384;
constexpr int NPIX = IDIM * JDIM;      // 147456
constexpr int CH   = 128;
constexpr int NH   = 4;
constexpr int HD   = 32;
constexpr float LN_EPS = 1e-5f;
constexpr float QSCALE = 0.17677669529663687f;  // 1/sqrt(32)

// Static device scratch
__device__ float g_xn[(size_t)NPIX * CH];
__device__ float g_qkvg[(size_t)NPIX * 512];     // q|k|v|g per pixel
__device__ float g_tri[(size_t)NH * NPIX];       // tri bias per head, (q,k) plane
__device__ float g_og[(size_t)NPIX * CH];

// ---------------------------------------------------------------------------
// helpers
// ---------------------------------------------------------------------------
__device__ __forceinline__ uint32_t f2tf(float f) {
    uint32_t u;
    asm("cvt.rna.tf32.f32 %0, %1;" : "=r"(u) : "f"(f));
    return u;
}

__device__ __forceinline__ void mma8(float* d, const uint32_t* a,
                                     uint32_t b0, uint32_t b1) {
    asm volatile(
        "mma.sync.aligned.m16n8k8.row.col.f32.tf32.tf32.f32 "
        "{%0,%1,%2,%3}, {%4,%5,%6,%7}, {%8,%9}, {%0,%1,%2,%3};\n"
        : "+f"(d[0]), "+f"(d[1]), "+f"(d[2]), "+f"(d[3])
        : "r"(a[0]), "r"(a[1]), "r"(a[2]), "r"(a[3]), "r"(b0), "r"(b1));
}

// ---------------------------------------------------------------------------
// Kernel 1: LayerNorm + triangle-bias projection (one warp per pixel)
// ---------------------------------------------------------------------------
__global__ void ln_tri_kernel(const float* __restrict__ x,
                              const float* __restrict__ ln_w,
                              const float* __restrict__ ln_b,
                              const float* __restrict__ w_tri) {
    int gw   = (blockIdx.x * blockDim.x + threadIdx.x) >> 5;
    int lane = threadIdx.x & 31;
    if (gw >= NPIX) return;

    const float4 xv = ((const float4*)(x + (size_t)gw * CH))[lane];

    float s = xv.x + xv.y + xv.z + xv.w;
    #pragma unroll
    for (int o = 16; o; o >>= 1) s += __shfl_xor_sync(0xffffffffu, s, o);
    float mu = s * (1.0f / 128.0f);

    float dx0 = xv.x - mu, dx1 = xv.y - mu, dx2 = xv.z - mu, dx3 = xv.w - mu;
    float vv = dx0*dx0 + dx1*dx1 + dx2*dx2 + dx3*dx3;
    #pragma unroll
    for (int o = 16; o; o >>= 1) vv += __shfl_xor_sync(0xffffffffu, vv, o);
    float rs = rsqrtf(vv * (1.0f / 128.0f) + LN_EPS);

    float4 w = ((const float4*)ln_w)[lane];
    float4 b = ((const float4*)ln_b)[lane];
    float4 xn;
    xn.x = dx0 * rs * w.x + b.x;
    xn.y = dx1 * rs * w.y + b.y;
    xn.z = dx2 * rs * w.z + b.z;
    xn.w = dx3 * rs * w.w + b.w;
    ((float4*)(g_xn + (size_t)gw * CH))[lane] = xn;

    const float4* wt = (const float4*)w_tri;
    float4 t0 = wt[lane * 4 + 0];
    float4 t1 = wt[lane * 4 + 1];
    float4 t2 = wt[lane * 4 + 2];
    float4 t3 = wt[lane * 4 + 3];
    float th0 = xn.x * t0.x + xn.y * t1.x + xn.z * t2.x + xn.w * t3.x;
    float th1 = xn.x * t0.y + xn.y * t1.y + xn.z * t2.y + xn.w * t3.y;
    float th2 = xn.x * t0.z + xn.y * t1.z + xn.z * t2.z + xn.w * t3.z;
    float th3 = xn.x * t0.w + xn.y * t1.w + xn.z * t2.w + xn.w * t3.w;
    #pragma unroll
    for (int o = 16; o; o >>= 1) {
        th0 += __shfl_xor_sync(0xffffffffu, th0, o);
        th1 += __shfl_xor_sync(0xffffffffu, th1, o);
        th2 += __shfl_xor_sync(0xffffffffu, th2, o);
        th3 += __shfl_xor_sync(0xffffffffu, th3, o);
    }
    if (lane == 0) {
        g_tri[0 * (size_t)NPIX + gw] = th0;
        g_tri[1 * (size_t)NPIX + gw] = th1;
        g_tri[2 * (size_t)NPIX + gw] = th2;
        g_tri[3 * (size_t)NPIX + gw] = th3;
    }
}

// ---------------------------------------------------------------------------
// Kernel 2: tf32 mma GEMM.  C[M,128*nw] = A[M,128] x W_i[128,128] (+bias on
// weight index bias_wi).  M-tile 128, full K=128 in smem, loops over nw
// weights reusing the staged A tile.  amode: 0 -> A=g_xn (write g_qkvg),
// 1 -> A=g_og (write Cext, ldc 128).
// ---------------------------------------------------------------------------
constexpr int PPAD = 132;
constexpr size_t SMEM_PROJ = (size_t)2 * 128 * PPAD * 4;

__global__ void __launch_bounds__(256) proj_kernel(
        const float* __restrict__ W0, const float* __restrict__ W1,
        const float* __restrict__ W2, const float* __restrict__ W3,
        const float* __restrict__ bias, int bias_wi, int nw,
        float* __restrict__ Cext, int amode) {
    extern __shared__ uint32_t smu[];
    uint32_t* Asu = smu;                      // [128][PPAD]
    uint32_t* Wtu = smu + 128 * PPAD;         // [128 n][PPAD] (transposed W)

    const float* A = (amode == 0) ? g_xn : g_og;
    const int bm  = blockIdx.x * 128;
    const int tid = threadIdx.x;
    const int w = tid >> 5, lane = tid & 31;
    const int g = lane >> 2, t = lane & 3;
    const int wm = w >> 1, wn = w & 1;        // warp tile: rows wm*32, cols wn*64

    // stage A (cvt to tf32)
    {
        int r = tid >> 1, half = tid & 1;
        const float4* src = (const float4*)(A + (size_t)(bm + r) * 128 + half * 64);
        uint32_t* dst = Asu + r * PPAD + half * 64;
        #pragma unroll
        for (int c = 0; c < 16; ++c) {
            float4 v = src[c];
            uint4 u = { f2tf(v.x), f2tf(v.y), f2tf(v.z), f2tf(v.w) };
            *(uint4*)(dst + c * 4) = u;
        }
    }

    const float* Ws[4] = { W0, W1, W2, W3 };

    for (int wi = 0; wi < nw; ++wi) {
        __syncthreads();
        // stage W transposed: Wt[n][k] = W[k][n]
        {
            int k = tid >> 1, half = tid & 1;
            const float4* src = (const float4*)(Ws[wi] + (size_t)k * 128 + half * 64);
            #pragma unroll
            for (int c = 0; c < 16; ++c) {
                float4 v = src[c];
                int n = half * 64 + c * 4;
                Wtu[(n + 0) * PPAD + k] = f2tf(v.x);
                Wtu[(n + 1) * PPAD + k] = f2tf(v.y);
                Wtu[(n + 2) * PPAD + k] = f2tf(v.z);
                Wtu[(n + 3) * PPAD + k] = f2tf(v.w);
            }
        }
        __syncthreads();

        float acc[2][8][4];
        #pragma unroll
        for (int mi = 0; mi < 2; ++mi)
            #pragma unroll
            for (int nt = 0; nt < 8; ++nt)
                #pragma unroll
                for (int j = 0; j < 4; ++j) acc[mi][nt][j] = 0.0f;

        #pragma unroll
        for (int kk = 0; kk < 16; ++kk) {
            uint32_t a[2][4];
            #pragma unroll
            for (int mi = 0; mi < 2; ++mi) {
                int rb = wm * 32 + mi * 16;
                a[mi][0] = Asu[(rb + g) * PPAD + kk * 8 + t];
                a[mi][1] = Asu[(rb + g + 8) * PPAD + kk * 8 + t];
                a[mi][2] = Asu[(rb + g) * PPAD + kk * 8 + t + 4];
                a[mi][3] = Asu[(rb + g + 8) * PPAD + kk * 8 + t + 4];
            }
            #pragma unroll
            for (int nt = 0; nt < 8; ++nt) {
                uint32_t b0 = Wtu[(wn * 64 + nt * 8 + g) * PPAD + kk * 8 + t];
                uint32_t b1 = Wtu[(wn * 64 + nt * 8 + g) * PPAD + kk * 8 + t + 4];
                mma8(acc[0][nt], a[0], b0, b1);
                mma8(acc[1][nt], a[1], b0, b1);
            }
        }

        // epilogue
        #pragma unroll
        for (int mi = 0; mi < 2; ++mi) {
            #pragma unroll
            for (int nt = 0; nt < 8; ++nt) {
                int row = bm + wm * 32 + mi * 16 + g;
                int col = wn * 64 + nt * 8 + 2 * t;
                float2 v0 = { acc[mi][nt][0], acc[mi][nt][1] };
                float2 v1 = { acc[mi][nt][2], acc[mi][nt][3] };
                if (bias && wi == bias_wi) {
                    float2 bb = *(const float2*)(bias + col);
                    v0.x += bb.x; v0.y += bb.y;
                    v1.x += bb.x; v1.y += bb.y;
                }
                if (amode == 0) {
                    *(float2*)(g_qkvg + (size_t)row * 512 + wi * 128 + col) = v0;
                    *(float2*)(g_qkvg + (size_t)(row + 8) * 512 + wi * 128 + col) = v1;
                } else {
                    *(float2*)(Cext + (size_t)row * 128 + col) = v0;
                    *(float2*)(Cext + (size_t)(row + 8) * 128 + col) = v1;
                }
            }
        }
    }
}

// ---------------------------------------------------------------------------
// Kernel 3: tf32 mma flash attention.
// Block = (q-tile 64, head, row i); 4 warps x 16 q-rows each.
// Keys permuted within 8-groups (sigma: c=2t+j -> key t+4j) so the S
// c-fragment layout IS the P a-fragment layout for the PV mma.
// Bias (tri + mask) loaded as the initial S accumulator.
// ---------------------------------------------------------------------------
__global__ void __launch_bounds__(128) attn_mma(const float* __restrict__ mask) {
    __shared__ float    Bs[64][72];   // bias tile, cols sigma-permuted
    __shared__ uint32_t Ks[64][36];   // tf32 K tile, rows sigma-permuted
    __shared__ uint32_t Vs[64][40];   // tf32 V tile, natural order

    const int qt  = blockIdx.x;       // 0..5
    const int h   = blockIdx.y;       // 0..3
    const int i   = blockIdx.z;       // 0..383
    const int tid = threadIdx.x;
    const int w = tid >> 5, lane = tid & 31;
    const int g = lane >> 2, t = lane & 3;
    const int q0 = qt * 64;

    // Q a-frags (scaled + tf32), 4 k-tiles over head-dim 32
    uint32_t qa[4][4];
    {
        int qr = q0 + w * 16 + g;
        const float* p0 = g_qkvg + ((size_t)i * JDIM + qr) * 512 + h * HD;
        const float* p1 = p0 + 8 * 512;
        #pragma unroll
        for (int kk = 0; kk < 4; ++kk) {
            qa[kk][0] = f2tf(QSCALE * p0[kk * 8 + t]);
            qa[kk][1] = f2tf(QSCALE * p1[kk * 8 + t]);
            qa[kk][2] = f2tf(QSCALE * p0[kk * 8 + t + 4]);
            qa[kk][3] = f2tf(QSCALE * p1[kk * 8 + t + 4]);
        }
    }

    float m0 = -1e30f, m1 = -1e30f, l0 = 0.0f, l1 = 0.0f;
    float o[4][4];
    #pragma unroll
    for (int nt = 0; nt < 4; ++nt)
        #pragma unroll
        for (int j = 0; j < 4; ++j) o[nt][j] = 0.0f;

    const float* trih = g_tri + (size_t)h * NPIX;
    const float* mrow = mask + (size_t)i * JDIM;

    const int sr = tid >> 1;                                     // staging row 0..63
    const int sh = tid & 1;
    const int pr = (sr & ~7) | (((sr & 3) << 1) | ((sr >> 2) & 1)); // sigma^-1

    for (int kt = 0; kt < 6; ++kt) {
        const int k0 = kt * 64;
        __syncthreads();
        // stage K (permuted rows) and V (natural), cvt to tf32
        {
            const float* base = g_qkvg + ((size_t)i * JDIM + k0 + sr) * 512 + h * HD + sh * 16;
            #pragma unroll
            for (int c = 0; c < 4; ++c) {
                float4 kv = *(const float4*)(base + 128 + c * 4);
                float4 vv = *(const float4*)(base + 256 + c * 4);
                uint4 ku = { f2tf(kv.x), f2tf(kv.y), f2tf(kv.z), f2tf(kv.w) };
                uint4 vu = { f2tf(vv.x), f2tf(vv.y), f2tf(vv.z), f2tf(vv.w) };
                *(uint4*)&Ks[pr][sh * 16 + c * 4] = ku;
                *(uint4*)&Vs[sr][sh * 16 + c * 4] = vu;
            }
        }
        // stage bias (tri + mask), sigma-permuted cols
        {
            const float* tr = trih + (size_t)(q0 + sr) * JDIM + k0 + sh * 32;
            const float* mr = mrow + k0 + sh * 32;
            #pragma unroll
            for (int c = 0; c < 8; ++c) {
                float4 tv = *(const float4*)(tr + c * 4);
                float4 mv = *(const float4*)(mr + c * 4);
                int kb = sh * 32 + c * 4;
                int b8 = kb & ~7;
                #pragma unroll
                for (int e = 0; e < 4; ++e) {
                    int kk = kb + e;
                    int pc = b8 | (((kk & 3) << 1) | ((kk >> 2) & 1));
                    float bv = (e == 0 ? tv.x : e == 1 ? tv.y : e == 2 ? tv.z : tv.w)
                             + 1e9f * ((e == 0 ? mv.x : e == 1 ? mv.y : e == 2 ? mv.z : mv.w) - 1.0f);
                    Bs[sr][pc] = bv;
                }
            }
        }
        __syncthreads();

        // S accumulators initialized with bias
        float s[8][4];
        const int rr = w * 16 + g;
        #pragma unroll
        for (int nt = 0; nt < 8; ++nt) {
            float2 b0 = *(const float2*)&Bs[rr][nt * 8 + 2 * t];
            float2 b1 = *(const float2*)&Bs[rr + 8][nt * 8 + 2 * t];
            s[nt][0] = b0.x; s[nt][1] = b0.y; s[nt][2] = b1.x; s[nt][3] = b1.y;
        }
        // S += Q K^T
        #pragma unroll
        for (int nt = 0; nt < 8; ++nt) {
            #pragma unroll
            for (int kk = 0; kk < 4; ++kk) {
                uint32_t b0 = Ks[nt * 8 + g][kk * 8 + t];
                uint32_t b1 = Ks[nt * 8 + g][kk * 8 + t + 4];
                mma8(s[nt], qa[kk], b0, b1);
            }
        }

        // online softmax (rows g and g+8)
        float cm0 = -1e30f, cm1 = -1e30f;
        #pragma unroll
        for (int nt = 0; nt < 8; ++nt) {
            cm0 = fmaxf(cm0, fmaxf(s[nt][0], s[nt][1]));
            cm1 = fmaxf(cm1, fmaxf(s[nt][2], s[nt][3]));
        }
        cm0 = fmaxf(cm0, __shfl_xor_sync(0xffffffffu, cm0, 1));
        cm0 = fmaxf(cm0, __shfl_xor_sync(0xffffffffu, cm0, 2));
        cm1 = fmaxf(cm1, __shfl_xor_sync(0xffffffffu, cm1, 1));
        cm1 = fmaxf(cm1, __shfl_xor_sync(0xffffffffu, cm1, 2));

        float nm0 = fmaxf(m0, cm0), nm1 = fmaxf(m1, cm1);
        float al0 = __expf(m0 - nm0), al1 = __expf(m1 - nm1);
        m0 = nm0; m1 = nm1;

        float ps0 = 0.0f, ps1 = 0.0f;
        #pragma unroll
        for (int nt = 0; nt < 8; ++nt) {
            s[nt][0] = __expf(s[nt][0] - nm0);
            s[nt][1] = __expf(s[nt][1] - nm0);
            s[nt][2] = __expf(s[nt][2] - nm1);
            s[nt][3] = __expf(s[nt][3] - nm1);
            ps0 += s[nt][0] + s[nt][1];
            ps1 += s[nt][2] + s[nt][3];
        }
        ps0 += __shfl_xor_sync(0xffffffffu, ps0, 1);
        ps0 += __shfl_xor_sync(0xffffffffu, ps0, 2);
        ps1 += __shfl_xor_sync(0xffffffffu, ps1, 1);
        ps1 += __shfl_xor_sync(0xffffffffu, ps1, 2);
        l0 = l0 * al0 + ps0;
        l1 = l1 * al1 + ps1;

        #pragma unroll
        for (int nt = 0; nt < 4; ++nt) {
            o[nt][0] *= al0; o[nt][1] *= al0;
            o[nt][2] *= al1; o[nt][3] *= al1;
        }

        // O += P V   (P a-frags = reordered S c-frags, thanks to sigma)
        #pragma unroll
        for (int kk = 0; kk < 8; ++kk) {
            uint32_t pa[4];
            pa[0] = f2tf(s[kk][0]);
            pa[1] = f2tf(s[kk][2]);
            pa[2] = f2tf(s[kk][1]);
            pa[3] = f2tf(s[kk][3]);
            #pragma unroll
            for (int nt = 0; nt < 4; ++nt) {
                uint32_t b0 = Vs[kk * 8 + t][nt * 8 + g];
                uint32_t b1 = Vs[kk * 8 + t + 4][nt * 8 + g];
                mma8(o[nt], pa, b0, b1);
            }
        }
    }

    // epilogue: normalize, gate, store
    float inv0 = 1.0f / l0, inv1 = 1.0f / l1;
    int qr = q0 + w * 16 + g;
    size_t pix0 = (size_t)i * JDIM + qr;
    size_t pix1 = pix0 + 8;
    const float* g0 = g_qkvg + pix0 * 512 + 384 + h * HD;
    const float* g1 = g_qkvg + pix1 * 512 + 384 + h * HD;
    float* o0 = g_og + pix0 * CH + h * HD;
    float* o1 = g_og + pix1 * CH + h * HD;
    #pragma unroll
    for (int nt = 0; nt < 4; ++nt) {
        int d = nt * 8 + 2 * t;
        float2 gv0 = *(const float2*)(g0 + d);
        float2 gv1 = *(const float2*)(g1 + d);
        float2 r0, r1;
        r0.x = o[nt][0] * inv0 * (1.0f / (1.0f + __expf(-gv0.x)));
        r0.y = o[nt][1] * inv0 * (1.0f / (1.0f + __expf(-gv0.y)));
        r1.x = o[nt][2] * inv1 * (1.0f / (1.0f + __expf(-gv1.x)));
        r1.y = o[nt][3] * inv1 * (1.0f / (1.0f + __expf(-gv1.y)));
        *(float2*)(o0 + d) = r0;
        *(float2*)(o1 + d) = r1;
    }
}

// ---------------------------------------------------------------------------
// Launch.  Inputs: x, mask, ln_w, ln_b, w_tri, wq, wk, wv, wg, bg, wo, bo
// ---------------------------------------------------------------------------
extern "C" void kernel_launch(void* const* d_in, const int* in_sizes, int n_in,
                              void* d_out, int out_size) {
    const float* x     = (const float*)d_in[0];
    const float* mask  = (const float*)d_in[1];
    const float* ln_w  = (const float*)d_in[2];
    const float* ln_b  = (const float*)d_in[3];
    const float* w_tri = (const float*)d_in[4];
    const float* wq    = (const float*)d_in[5];
    const float* wk    = (const float*)d_in[6];
    const float* wv    = (const float*)d_in[7];
    const float* wg    = (const float*)d_in[8];
    const float* bg    = (const float*)d_in[9];
    const float* wo    = (const float*)d_in[10];
    const float* bo    = (const float*)d_in[11];
    float* out = (float*)d_out;

    static bool attr_done = false;
    if (!attr_done) {
        cudaFuncSetAttribute(proj_kernel,
                             cudaFuncAttributeMaxDynamicSharedMemorySize,
                             (int)SMEM_PROJ);
        attr_done = true;
    }

    ln_tri_kernel<<<NPIX / 8, 256>>>(x, ln_w, ln_b, w_tri);

    // fused q,k,v,g projections (tensor cores)
    proj_kernel<<<NPIX / 128, 256, SMEM_PROJ>>>(wq, wk, wv, wg, bg, 3, 4,
                                                nullptr, 0);

    // attention
    attn_mma<<<dim3(6, NH, IDIM), 128>>>(mask);

    // output projection
    proj_kernel<<<NPIX / 128, 256, SMEM_PROJ>>>(wo, wo, wo, wo, bo, 0, 1,
                                                out, 1);
}

// round 3
// speedup vs baseline: 2.5654x; 1.4761x over previous
#include <cuda_runtime.h>
#include <cstdint>

constexpr int IDIM = 384;
constexpr int JDIM = 384;
constexpr int NPIX = IDIM * JDIM;      // 147456
constexpr int CH   = 128;
constexpr int NH   = 4;
constexpr int HD   = 32;
constexpr float LN_EPS = 1e-5f;
constexpr float QSCALE = 0.17677669529663687f;  // 1/sqrt(32)

// Static device scratch
__device__ float g_qkvg[(size_t)NPIX * 512];   // q|k|v|g per pixel (q,k,v stored as tf32 bit patterns, q pre-scaled)
__device__ float g_tri[(size_t)NH * NPIX];     // tri bias, k-index sigma-permuted
__device__ float g_mb[(size_t)NPIX];           // 1e9*(mask-1), k-index sigma-permuted
__device__ float g_og[(size_t)NPIX * CH];      // gated attention output

// ---------------------------------------------------------------------------
__device__ __forceinline__ uint32_t f2tf(float f) {
    uint32_t u;
    asm("cvt.rna.tf32.f32 %0, %1;" : "=r"(u) : "f"(f));
    return u;
}
__device__ __forceinline__ void mma8(float* d, const uint32_t* a,
                                     uint32_t b0, uint32_t b1) {
    asm volatile(
        "mma.sync.aligned.m16n8k8.row.col.f32.tf32.tf32.f32 "
        "{%0,%1,%2,%3}, {%4,%5,%6,%7}, {%8,%9}, {%0,%1,%2,%3};\n"
        : "+f"(d[0]), "+f"(d[1]), "+f"(d[2]), "+f"(d[3])
        : "r"(a[0]), "r"(a[1]), "r"(a[2]), "r"(a[3]), "r"(b0), "r"(b1));
}
// sigma permutation within groups of 8 (same map verified in round 2)
__device__ __forceinline__ int perm8(int x) {
    return (x & ~7) | (((x & 3) << 1) | ((x >> 2) & 1));
}

// ---------------------------------------------------------------------------
// Kernel 0: permuted mask-bias rows
// ---------------------------------------------------------------------------
__global__ void maskb_kernel(const float* __restrict__ mask) {
    int idx = blockIdx.x * 256 + threadIdx.x;
    if (idx >= NPIX) return;
    int i = idx / JDIM;
    int j = idx - i * JDIM;
    g_mb[(size_t)i * JDIM + perm8(j)] = 1e9f * (mask[idx] - 1.0f);
}

// ---------------------------------------------------------------------------
// Kernel 1: fused {LayerNorm + tri-proj} + tf32 mma projections.
// amode 0: X = x, LN applied, writes q|k|v|g (+tri permuted); 512 thr, M=256.
// amode 1: X ignored, A = g_og, writes Cext (out proj).
// Pair-permuted smem columns -> all fragment loads are LDS.64.
// ---------------------------------------------------------------------------
constexpr int PPAD = 136;   // stride mod 32 == 8 -> conflict-free LDS.64
constexpr size_t SMEM_PROJ = (size_t)(256 * PPAD + 128 * PPAD + 768) * 4;

__global__ void __launch_bounds__(512) proj_kernel(
        const float* __restrict__ W0, const float* __restrict__ W1,
        const float* __restrict__ W2, const float* __restrict__ W3,
        const float* __restrict__ bias, int bias_wi, int nw,
        const float* __restrict__ X,
        const float* __restrict__ ln_w, const float* __restrict__ ln_b,
        const float* __restrict__ w_tri,
        float* __restrict__ Cext, int amode) {
    extern __shared__ uint32_t smu[];
    uint32_t* Asu = smu;                    // [256][PPAD]
    uint32_t* Wtu = smu + 256 * PPAD;       // [128][PPAD] transposed W, k pair-permuted
    float* lnw  = (float*)(Wtu + 128 * PPAD);
    float* lnb  = lnw + 128;
    float* wtri = lnb + 128;                // 512 floats

    const int tid = threadIdx.x;
    const int bm  = blockIdx.x * 256;

    if (amode == 0) {
        if (tid < 32)        ((float4*)lnw)[tid]       = ((const float4*)ln_w)[tid];
        else if (tid < 64)   ((float4*)lnb)[tid - 32]  = ((const float4*)ln_b)[tid - 32];
        else if (tid < 192)  ((float4*)wtri)[tid - 64] = ((const float4*)w_tri)[tid - 64];
    }
    __syncthreads();

    // ---- stage A (LN + tri for amode 0) ----
    {
        int r = tid >> 1, half = tid & 1;
        int gw = bm + r;
        const float4* xr = (const float4*)(
            ((amode == 0) ? X : g_og) + (size_t)gw * 128 + half * 64);
        uint32_t* arow = Asu + r * PPAD;

        if (amode == 0) {
            float s = 0.f, ss = 0.f;
            #pragma unroll
            for (int c = 0; c < 16; ++c) {
                float4 v = xr[c];
                s  += v.x + v.y + v.z + v.w;
                ss += v.x * v.x + v.y * v.y + v.z * v.z + v.w * v.w;
            }
            s  += __shfl_xor_sync(0xffffffffu, s, 1);
            ss += __shfl_xor_sync(0xffffffffu, ss, 1);
            float mu = s * (1.0f / 128.0f);
            float rs = rsqrtf(fmaxf(ss * (1.0f / 128.0f) - mu * mu, 0.f) + LN_EPS);

            float th0 = 0.f, th1 = 0.f, th2 = 0.f, th3 = 0.f;
            #pragma unroll
            for (int c = 0; c < 16; ++c) {
                float4 v = xr[c];
                float vs[4] = { v.x, v.y, v.z, v.w };
                #pragma unroll
                for (int e = 0; e < 4; ++e) {
                    int ch = half * 64 + c * 4 + e;
                    float xn = (vs[e] - mu) * rs * lnw[ch] + lnb[ch];
                    float4 wt = ((const float4*)wtri)[ch];
                    th0 += xn * wt.x; th1 += xn * wt.y;
                    th2 += xn * wt.z; th3 += xn * wt.w;
                    arow[perm8(ch)] = f2tf(xn);
                }
            }
            th0 += __shfl_xor_sync(0xffffffffu, th0, 1);
            th1 += __shfl_xor_sync(0xffffffffu, th1, 1);
            th2 += __shfl_xor_sync(0xffffffffu, th2, 1);
            th3 += __shfl_xor_sync(0xffffffffu, th3, 1);
            if (half == 0) {
                size_t dst = (size_t)((gw & ~7) | (((gw & 3) << 1) | ((gw >> 2) & 1)));
                g_tri[0 * (size_t)NPIX + dst] = th0;
                g_tri[1 * (size_t)NPIX + dst] = th1;
                g_tri[2 * (size_t)NPIX + dst] = th2;
                g_tri[3 * (size_t)NPIX + dst] = th3;
            }
        } else {
            #pragma unroll
            for (int c = 0; c < 16; ++c) {
                float4 v = xr[c];
                float vs[4] = { v.x, v.y, v.z, v.w };
                #pragma unroll
                for (int e = 0; e < 4; ++e) {
                    int ch = half * 64 + c * 4 + e;
                    arow[perm8(ch)] = f2tf(vs[e]);
                }
            }
        }
    }

    const float* Ws[4] = { W0, W1, W2, W3 };
    const int w = tid >> 5, lane = tid & 31;
    const int g = lane >> 2, t = lane & 3;
    const int wm = w >> 1, wn = w & 1;        // wm 0..7 (32 rows), wn 0..1 (64 cols)

    for (int wi = 0; wi < nw; ++wi) {
        __syncthreads();
        // stage W transposed, k pair-permuted
        {
            int k = tid >> 2, q4 = tid & 3;
            int pk = perm8(k);
            const float4* wr = (const float4*)(Ws[wi] + (size_t)k * 128 + q4 * 32);
            #pragma unroll
            for (int c = 0; c < 8; ++c) {
                float4 v = wr[c];
                int n = q4 * 32 + c * 4;
                Wtu[(n + 0) * PPAD + pk] = f2tf(v.x);
                Wtu[(n + 1) * PPAD + pk] = f2tf(v.y);
                Wtu[(n + 2) * PPAD + pk] = f2tf(v.z);
                Wtu[(n + 3) * PPAD + pk] = f2tf(v.w);
            }
        }
        __syncthreads();

        float acc[2][8][4];
        #pragma unroll
        for (int mi = 0; mi < 2; ++mi)
            #pragma unroll
            for (int nt = 0; nt < 8; ++nt)
                #pragma unroll
                for (int j = 0; j < 4; ++j) acc[mi][nt][j] = 0.0f;

        #pragma unroll
        for (int kk = 0; kk < 16; ++kk) {
            uint32_t a[2][4];
            #pragma unroll
            for (int mi = 0; mi < 2; ++mi) {
                int rb = wm * 32 + mi * 16;
                uint64_t p0 = *(const uint64_t*)&Asu[(rb + g) * PPAD + kk * 8 + 2 * t];
                uint64_t p1 = *(const uint64_t*)&Asu[(rb + g + 8) * PPAD + kk * 8 + 2 * t];
                a[mi][0] = (uint32_t)p0; a[mi][2] = (uint32_t)(p0 >> 32);
                a[mi][1] = (uint32_t)p1; a[mi][3] = (uint32_t)(p1 >> 32);
            }
            #pragma unroll
            for (int nt = 0; nt < 8; ++nt) {
                uint64_t bp = *(const uint64_t*)&Wtu[(wn * 64 + nt * 8 + g) * PPAD + kk * 8 + 2 * t];
                mma8(acc[0][nt], a[0], (uint32_t)bp, (uint32_t)(bp >> 32));
                mma8(acc[1][nt], a[1], (uint32_t)bp, (uint32_t)(bp >> 32));
            }
        }

        // epilogue
        #pragma unroll
        for (int mi = 0; mi < 2; ++mi) {
            #pragma unroll
            for (int nt = 0; nt < 8; ++nt) {
                int row = bm + wm * 32 + mi * 16 + g;
                int col = wn * 64 + nt * 8 + 2 * t;
                float v0 = acc[mi][nt][0], v1 = acc[mi][nt][1];
                float v2 = acc[mi][nt][2], v3 = acc[mi][nt][3];
                if (amode == 0) {
                    float2 r0, r1;
                    if (wi == 0) {          // q: pre-scale + tf32 round
                        r0.x = __uint_as_float(f2tf(QSCALE * v0));
                        r0.y = __uint_as_float(f2tf(QSCALE * v1));
                        r1.x = __uint_as_float(f2tf(QSCALE * v2));
                        r1.y = __uint_as_float(f2tf(QSCALE * v3));
                    } else if (wi < 3) {    // k, v: tf32 round
                        r0.x = __uint_as_float(f2tf(v0));
                        r0.y = __uint_as_float(f2tf(v1));
                        r1.x = __uint_as_float(f2tf(v2));
                        r1.y = __uint_as_float(f2tf(v3));
                    } else {                // g: + bias, fp32
                        float2 bb = *(const float2*)(bias + col);
                        r0 = { v0 + bb.x, v1 + bb.y };
                        r1 = { v2 + bb.x, v3 + bb.y };
                    }
                    *(float2*)(g_qkvg + (size_t)row * 512 + wi * 128 + col) = r0;
                    *(float2*)(g_qkvg + (size_t)(row + 8) * 512 + wi * 128 + col) = r1;
                } else {
                    float2 bb = *(const float2*)(bias + col);
                    float2 r0 = { v0 + bb.x, v1 + bb.y };
                    float2 r1 = { v2 + bb.x, v3 + bb.y };
                    *(float2*)(Cext + (size_t)row * 128 + col) = r0;
                    *(float2*)(Cext + (size_t)(row + 8) * 128 + col) = r1;
                }
            }
        }
    }
}

// ---------------------------------------------------------------------------
// Kernel 2: tf32 mma flash attention, q-tile 128, 256 threads (8 warps).
// K tile rows sigma-permuted, dims pair-permuted; V transposed with keys
// pair-permuted -> all fragment loads LDS.64. Bias init from permuted tri
// (coalesced LDG.64, L2-resident) + permuted mask row (smem).
// ---------------------------------------------------------------------------
__global__ void __launch_bounds__(256) attn_mma() {
    __shared__ __align__(16) uint32_t Ks[64][40];  // stride 40 mod 32 == 8
    __shared__ __align__(16) uint32_t Vt[32][72];  // stride 72 mod 32 == 8
    __shared__ __align__(16) float mb[384];

    const int qt  = blockIdx.x;       // 0..2
    const int h   = blockIdx.y;       // 0..3
    const int i   = blockIdx.z;       // 0..383
    const int tid = threadIdx.x;
    const int w = tid >> 5, lane = tid & 31;
    const int g = lane >> 2, t = lane & 3;
    const int q0 = qt * 128;

    if (tid < 96)
        ((float4*)mb)[tid] = *(const float4*)(g_mb + (size_t)i * JDIM + tid * 4);

    // Q fragments (stored pre-scaled tf32 bit patterns)
    uint32_t qa[4][4];
    const int qr = q0 + w * 16 + g;
    {
        const float* p0 = g_qkvg + ((size_t)i * JDIM + qr) * 512 + h * HD;
        const float* p1 = p0 + 8 * 512;
        #pragma unroll
        for (int kk = 0; kk < 4; ++kk) {
            qa[kk][0] = __float_as_uint(p0[kk * 8 + t]);
            qa[kk][1] = __float_as_uint(p1[kk * 8 + t]);
            qa[kk][2] = __float_as_uint(p0[kk * 8 + t + 4]);
            qa[kk][3] = __float_as_uint(p1[kk * 8 + t + 4]);
        }
    }

    float m0 = -1e30f, m1 = -1e30f, l0 = 0.0f, l1 = 0.0f;
    float o[4][4];
    #pragma unroll
    for (int nt = 0; nt < 4; ++nt)
        #pragma unroll
        for (int j = 0; j < 4; ++j) o[nt][j] = 0.0f;

    const int sr = tid >> 2, sh = tid & 3;     // staging: key row, dim quarter
    const int pr = perm8(sr);                  // physical = perm8(logical)
    const float* trow0 = g_tri + (size_t)h * NPIX + (size_t)qr * JDIM;
    const float* trow1 = trow0 + 8 * JDIM;

    for (int kt = 0; kt < 6; ++kt) {
        const int k0 = kt * 64;
        __syncthreads();
        // stage K (row-permuted, dim pair-permuted) and V^T (key pair-permuted)
        {
            const float* kb = g_qkvg + ((size_t)i * JDIM + k0 + sr) * 512 + 128 + h * HD + sh * 8;
            float4 ka = *(const float4*)kb;
            float4 kc = *(const float4*)(kb + 4);
            float4 va = *(const float4*)(kb + 128);
            float4 vc = *(const float4*)(kb + 132);
            uint32_t* kr = &Ks[pr][sh * 8];
            kr[0] = __float_as_uint(ka.x);  kr[2] = __float_as_uint(ka.y);
            kr[4] = __float_as_uint(ka.z);  kr[6] = __float_as_uint(ka.w);
            kr[1] = __float_as_uint(kc.x);  kr[3] = __float_as_uint(kc.y);
            kr[5] = __float_as_uint(kc.z);  kr[7] = __float_as_uint(kc.w);
            int d0 = sh * 8;
            Vt[d0 + 0][pr] = __float_as_uint(va.x);
            Vt[d0 + 1][pr] = __float_as_uint(va.y);
            Vt[d0 + 2][pr] = __float_as_uint(va.z);
            Vt[d0 + 3][pr] = __float_as_uint(va.w);
            Vt[d0 + 4][pr] = __float_as_uint(vc.x);
            Vt[d0 + 5][pr] = __float_as_uint(vc.y);
            Vt[d0 + 6][pr] = __float_as_uint(vc.z);
            Vt[d0 + 7][pr] = __float_as_uint(vc.w);
        }

        // S init from permuted tri (gmem, overlaps the barrier below)
        float s[8][4];
        #pragma unroll
        for (int nt = 0; nt < 8; ++nt) {
            float2 a = *(const float2*)(trow0 + k0 + nt * 8 + 2 * t);
            float2 b = *(const float2*)(trow1 + k0 + nt * 8 + 2 * t);
            s[nt][0] = a.x; s[nt][1] = a.y; s[nt][2] = b.x; s[nt][3] = b.y;
        }
        __syncthreads();

        // + mask bias, then S += Q K^T
        #pragma unroll
        for (int nt = 0; nt < 8; ++nt) {
            float2 mv = *(const float2*)&mb[k0 + nt * 8 + 2 * t];
            s[nt][0] += mv.x; s[nt][1] += mv.y;
            s[nt][2] += mv.x; s[nt][3] += mv.y;
            #pragma unroll
            for (int kk = 0; kk < 4; ++kk) {
                uint64_t bp = *(const uint64_t*)&Ks[nt * 8 + g][kk * 8 + 2 * t];
                mma8(s[nt], qa[kk], (uint32_t)bp, (uint32_t)(bp >> 32));
            }
        }

        // online softmax (rows g, g+8)
        float cm0 = -1e30f, cm1 = -1e30f;
        #pragma unroll
        for (int nt = 0; nt < 8; ++nt) {
            cm0 = fmaxf(cm0, fmaxf(s[nt][0], s[nt][1]));
            cm1 = fmaxf(cm1, fmaxf(s[nt][2], s[nt][3]));
        }
        cm0 = fmaxf(cm0, __shfl_xor_sync(0xffffffffu, cm0, 1));
        cm0 = fmaxf(cm0, __shfl_xor_sync(0xffffffffu, cm0, 2));
        cm1 = fmaxf(cm1, __shfl_xor_sync(0xffffffffu, cm1, 1));
        cm1 = fmaxf(cm1, __shfl_xor_sync(0xffffffffu, cm1, 2));

        float nm0 = fmaxf(m0, cm0), nm1 = fmaxf(m1, cm1);
        float al0 = __expf(m0 - nm0), al1 = __expf(m1 - nm1);
        m0 = nm0; m1 = nm1;

        float ps0 = 0.0f, ps1 = 0.0f;
        #pragma unroll
        for (int nt = 0; nt < 8; ++nt) {
            s[nt][0] = __expf(s[nt][0] - nm0);
            s[nt][1] = __expf(s[nt][1] - nm0);
            s[nt][2] = __expf(s[nt][2] - nm1);
            s[nt][3] = __expf(s[nt][3] - nm1);
            ps0 += s[nt][0] + s[nt][1];
            ps1 += s[nt][2] + s[nt][3];
        }
        ps0 += __shfl_xor_sync(0xffffffffu, ps0, 1);
        ps0 += __shfl_xor_sync(0xffffffffu, ps0, 2);
        ps1 += __shfl_xor_sync(0xffffffffu, ps1, 1);
        ps1 += __shfl_xor_sync(0xffffffffu, ps1, 2);
        l0 = l0 * al0 + ps0;
        l1 = l1 * al1 + ps1;

        #pragma unroll
        for (int nt = 0; nt < 4; ++nt) {
            o[nt][0] *= al0; o[nt][1] *= al0;
            o[nt][2] *= al1; o[nt][3] *= al1;
        }

        // O += P V  (P a-frags = reordered S c-frags; V keys pair-permuted)
        #pragma unroll
        for (int kk = 0; kk < 8; ++kk) {
            uint32_t pa[4];
            pa[0] = f2tf(s[kk][0]);
            pa[1] = f2tf(s[kk][2]);
            pa[2] = f2tf(s[kk][1]);
            pa[3] = f2tf(s[kk][3]);
            #pragma unroll
            for (int nt = 0; nt < 4; ++nt) {
                uint64_t bp = *(const uint64_t*)&Vt[nt * 8 + g][kk * 8 + 2 * t];
                mma8(o[nt], pa, (uint32_t)bp, (uint32_t)(bp >> 32));
            }
        }
    }

    // epilogue: normalize, gate, store
    float inv0 = 1.0f / l0, inv1 = 1.0f / l1;
    size_t pix0 = (size_t)i * JDIM + qr;
    size_t pix1 = pix0 + 8;
    const float* g0 = g_qkvg + pix0 * 512 + 384 + h * HD;
    const float* g1 = g_qkvg + pix1 * 512 + 384 + h * HD;
    float* o0 = g_og + pix0 * CH + h * HD;
    float* o1 = g_og + pix1 * CH + h * HD;
    #pragma unroll
    for (int nt = 0; nt < 4; ++nt) {
        int d = nt * 8 + 2 * t;
        float2 gv0 = *(const float2*)(g0 + d);
        float2 gv1 = *(const float2*)(g1 + d);
        float2 r0, r1;
        r0.x = o[nt][0] * inv0 * (1.0f / (1.0f + __expf(-gv0.x)));
        r0.y = o[nt][1] * inv0 * (1.0f / (1.0f + __expf(-gv0.y)));
        r1.x = o[nt][2] * inv1 * (1.0f / (1.0f + __expf(-gv1.x)));
        r1.y = o[nt][3] * inv1 * (1.0f / (1.0f + __expf(-gv1.y)));
        *(float2*)(o0 + d) = r0;
        *(float2*)(o1 + d) = r1;
    }
}

// ---------------------------------------------------------------------------
// Launch.  Inputs: x, mask, ln_w, ln_b, w_tri, wq, wk, wv, wg, bg, wo, bo
// ---------------------------------------------------------------------------
extern "C" void kernel_launch(void* const* d_in, const int* in_sizes, int n_in,
                              void* d_out, int out_size) {
    const float* x     = (const float*)d_in[0];
    const float* mask  = (const float*)d_in[1];
    const float* ln_w  = (const float*)d_in[2];
    const float* ln_b  = (const float*)d_in[3];
    const float* w_tri = (const float*)d_in[4];
    const float* wq    = (const float*)d_in[5];
    const float* wk    = (const float*)d_in[6];
    const float* wv    = (const float*)d_in[7];
    const float* wg    = (const float*)d_in[8];
    const float* bg    = (const float*)d_in[9];
    const float* wo    = (const float*)d_in[10];
    const float* bo    = (const float*)d_in[11];
    float* out = (float*)d_out;

    static bool attr_done = false;
    if (!attr_done) {
        cudaFuncSetAttribute(proj_kernel,
                             cudaFuncAttributeMaxDynamicSharedMemorySize,
                             (int)SMEM_PROJ);
        attr_done = true;
    }

    maskb_kernel<<<(NPIX + 255) / 256, 256>>>(mask);

    // fused LN + tri + q,k,v,g projections
    proj_kernel<<<NPIX / 256, 512, SMEM_PROJ>>>(wq, wk, wv, wg, bg, 3, 4,
                                                x, ln_w, ln_b, w_tri,
                                                nullptr, 0);

    // attention (tri + mask bias, gating fused)
    attn_mma<<<dim3(3, NH, IDIM), 256>>>();

    // output projection
    proj_kernel<<<NPIX / 256, 512, SMEM_PROJ>>>(wo, wo, wo, wo, bo, 0, 1,
                                                nullptr, nullptr, nullptr, nullptr,
                                                out, 1);
}

// round 4
// speedup vs baseline: 2.6493x; 1.0327x over previous
#include <cuda_runtime.h>
#include <cstdint>

constexpr int IDIM = 384;
constexpr int JDIM = 384;
constexpr int NPIX = IDIM * JDIM;      // 147456
constexpr int CH   = 128;
constexpr int NH   = 4;
constexpr int HD   = 32;
constexpr float LN_EPS = 1e-5f;
constexpr float QSCALE = 0.17677669529663687f;  // 1/sqrt(32)
constexpr float LOG2E  = 1.4426950408889634f;

// Static device scratch
__device__ float g_qkvg[(size_t)NPIX * 512];   // q|k|v|g (q,k,v tf32 bits; q,k slot-interleaved; k rows perm'd; q pre-scaled by QSCALE*log2e)
__device__ float g_tri[(size_t)NH * NPIX];     // tri bias * log2e, k-index perm'd
__device__ float g_mb[(size_t)NPIX];           // 1e9*log2e*(mask-1), k-index perm'd
__device__ float g_og[(size_t)NPIX * CH];      // gated attn out, slot-interleaved, tf32 bits
__device__ uint32_t g_wt[5][128][128];         // transposed tf32 weights, k pair-perm'd

// ---------------------------------------------------------------------------
__device__ __forceinline__ uint32_t f2tf(float f) {
    uint32_t u;
    asm("cvt.rna.tf32.f32 %0, %1;" : "=r"(u) : "f"(f));
    return u;
}
__device__ __forceinline__ float ex2(float x) {
    float y;
    asm("ex2.approx.f32 %0, %1;" : "=f"(y) : "f"(x));
    return y;
}
__device__ __forceinline__ void mma8(float* d, const uint32_t* a,
                                     uint32_t b0, uint32_t b1) {
    asm volatile(
        "mma.sync.aligned.m16n8k8.row.col.f32.tf32.tf32.f32 "
        "{%0,%1,%2,%3}, {%4,%5,%6,%7}, {%8,%9}, {%0,%1,%2,%3};\n"
        : "+f"(d[0]), "+f"(d[1]), "+f"(d[2]), "+f"(d[3])
        : "r"(a[0]), "r"(a[1]), "r"(a[2]), "r"(a[3]), "r"(b0), "r"(b1));
}
// sigma permutation within groups of 8 (fragment row/col map)
__device__ __forceinline__ int perm8(int x) {
    return (x & ~7) | (((x & 3) << 1) | ((x >> 2) & 1));
}
// slot interleave within groups of 8 (dim d -> slot): d<4 -> 2d, else 2(d-4)+1
__device__ __forceinline__ int slot8(int x) {
    int w = x & 7;
    return (x & ~7) | ((w < 4) ? (2 * w) : (2 * (w - 4) + 1));
}

// ---------------------------------------------------------------------------
// Kernel A: one-shot weight prep (transpose + tf32 + k pair-perm + q scale)
// ---------------------------------------------------------------------------
__global__ void prepw_kernel(const float* __restrict__ wq,
                             const float* __restrict__ wk,
                             const float* __restrict__ wv,
                             const float* __restrict__ wg,
                             const float* __restrict__ wo) {
    const float* Ws[5] = { wq, wk, wv, wg, wo };
    int wi = blockIdx.x;
    int k  = threadIdx.x;            // 128 threads: one K-row each
    float scale = (wi == 0) ? (QSCALE * LOG2E) : 1.0f;
    const float4* src = (const float4*)(Ws[wi] + (size_t)k * 128);
    int pk = perm8(k);
    #pragma unroll
    for (int c = 0; c < 32; ++c) {
        float4 v = src[c];
        g_wt[wi][c * 4 + 0][pk] = f2tf(v.x * scale);
        g_wt[wi][c * 4 + 1][pk] = f2tf(v.y * scale);
        g_wt[wi][c * 4 + 2][pk] = f2tf(v.z * scale);
        g_wt[wi][c * 4 + 3][pk] = f2tf(v.w * scale);
    }
}

// ---------------------------------------------------------------------------
// Kernel B: permuted, log2e-scaled mask-bias rows
// ---------------------------------------------------------------------------
__global__ void maskb_kernel(const float* __restrict__ mask) {
    int idx = blockIdx.x * 256 + threadIdx.x;
    if (idx >= NPIX) return;
    int i = idx / JDIM;
    int j = idx - i * JDIM;
    g_mb[(size_t)i * JDIM + perm8(j)] = (1e9f * LOG2E) * (mask[idx] - 1.0f);
}

// ---------------------------------------------------------------------------
// Kernel C: fused {LayerNorm + tri-proj} + tf32 mma projections.
// amode 0: X = x, LN applied, 4 weights -> q|k|v|g (+tri).
// amode 1: A = g_og (pre-slotted tf32), 1 weight -> Cext + bias.
// ---------------------------------------------------------------------------
constexpr int PPAD = 136;   // stride mod 32 == 8 -> conflict-free frag LDS.64
constexpr size_t SMEM_PROJ = (size_t)(256 * PPAD + 128 * PPAD + 768) * 4;

__global__ void __launch_bounds__(512) proj_kernel(
        int wbase, int nw, const float* __restrict__ bias, int bias_wi,
        const float* __restrict__ X,
        const float* __restrict__ ln_w, const float* __restrict__ ln_b,
        const float* __restrict__ w_tri,
        float* __restrict__ Cext, int amode) {
    extern __shared__ uint32_t smu[];
    uint32_t* Asu = smu;                    // [256][PPAD]
    uint32_t* Wtu = smu + 256 * PPAD;       // [128][PPAD]
    float* lnw  = (float*)(Wtu + 128 * PPAD);
    float* lnb  = lnw + 128;
    float* wtri = lnb + 128;                // 512 floats

    const int tid = threadIdx.x;
    const int bm  = blockIdx.x * 256;

    if (amode == 0) {
        if (tid < 32)        ((float4*)lnw)[tid]       = ((const float4*)ln_w)[tid];
        else if (tid < 64)   ((float4*)lnb)[tid - 32]  = ((const float4*)ln_b)[tid - 32];
        else if (tid < 192)  ((float4*)wtri)[tid - 64] = ((const float4*)w_tri)[tid - 64];
    }
    __syncthreads();

    // ---- stage A ----
    {
        int r = tid >> 1, half = tid & 1;
        int gw = bm + r;
        uint32_t* arow = Asu + r * PPAD;

        if (amode == 0) {
            const float4* xr = (const float4*)(X + (size_t)gw * 128 + half * 64);
            float s = 0.f, ss = 0.f;
            #pragma unroll
            for (int c = 0; c < 16; ++c) {
                float4 v = xr[c];
                s  += v.x + v.y + v.z + v.w;
                ss += v.x * v.x + v.y * v.y + v.z * v.z + v.w * v.w;
            }
            s  += __shfl_xor_sync(0xffffffffu, s, 1);
            ss += __shfl_xor_sync(0xffffffffu, ss, 1);
            float mu = s * (1.0f / 128.0f);
            float rs = rsqrtf(fmaxf(ss * (1.0f / 128.0f) - mu * mu, 0.f) + LN_EPS);

            float th0 = 0.f, th1 = 0.f, th2 = 0.f, th3 = 0.f;
            #pragma unroll
            for (int c = 0; c < 16; ++c) {
                float4 v = xr[c];
                float vs[4] = { v.x, v.y, v.z, v.w };
                #pragma unroll
                for (int e = 0; e < 4; ++e) {
                    int ch = half * 64 + c * 4 + e;
                    float xn = (vs[e] - mu) * rs * lnw[ch] + lnb[ch];
                    float4 wt = ((const float4*)wtri)[ch];
                    th0 += xn * wt.x; th1 += xn * wt.y;
                    th2 += xn * wt.z; th3 += xn * wt.w;
                    arow[perm8(ch)] = f2tf(xn);
                }
            }
            th0 += __shfl_xor_sync(0xffffffffu, th0, 1);
            th1 += __shfl_xor_sync(0xffffffffu, th1, 1);
            th2 += __shfl_xor_sync(0xffffffffu, th2, 1);
            th3 += __shfl_xor_sync(0xffffffffu, th3, 1);
            if (half == 0) {
                size_t dst = (size_t)perm8(gw);
                g_tri[0 * (size_t)NPIX + dst] = th0 * LOG2E;
                g_tri[1 * (size_t)NPIX + dst] = th1 * LOG2E;
                g_tri[2 * (size_t)NPIX + dst] = th2 * LOG2E;
                g_tri[3 * (size_t)NPIX + dst] = th3 * LOG2E;
            }
        } else {
            // g_og already slot-interleaved tf32 bits: straight copy
            const float4* xr = (const float4*)(g_og + (size_t)gw * 128 + half * 64);
            #pragma unroll
            for (int c = 0; c < 16; ++c)
                *(float4*)(arow + half * 64 + c * 4) = xr[c];
        }
    }

    const int w = tid >> 5, lane = tid & 31;
    const int g = lane >> 2, t = lane & 3;
    const int wm = w >> 1, wn = w & 1;

    for (int wi = 0; wi < nw; ++wi) {
        __syncthreads();
        // stage W: straight copy from prepped gmem
        {
            int n = tid >> 2, q4 = tid & 3;
            const float4* src = (const float4*)&g_wt[wbase + wi][n][q4 * 32];
            uint32_t* dst = Wtu + n * PPAD + q4 * 32;
            #pragma unroll
            for (int c = 0; c < 8; ++c)
                *(float4*)(dst + c * 4) = src[c];
        }
        __syncthreads();

        float acc[2][8][4];
        #pragma unroll
        for (int mi = 0; mi < 2; ++mi)
            #pragma unroll
            for (int nt = 0; nt < 8; ++nt)
                #pragma unroll
                for (int j = 0; j < 4; ++j) acc[mi][nt][j] = 0.0f;

        #pragma unroll
        for (int kk = 0; kk < 16; ++kk) {
            uint32_t a[2][4];
            #pragma unroll
            for (int mi = 0; mi < 2; ++mi) {
                int rb = wm * 32 + mi * 16;
                uint64_t p0 = *(const uint64_t*)&Asu[(rb + g) * PPAD + kk * 8 + 2 * t];
                uint64_t p1 = *(const uint64_t*)&Asu[(rb + g + 8) * PPAD + kk * 8 + 2 * t];
                a[mi][0] = (uint32_t)p0; a[mi][2] = (uint32_t)(p0 >> 32);
                a[mi][1] = (uint32_t)p1; a[mi][3] = (uint32_t)(p1 >> 32);
            }
            #pragma unroll
            for (int nt = 0; nt < 8; ++nt) {
                uint64_t bp = *(const uint64_t*)&Wtu[(wn * 64 + nt * 8 + g) * PPAD + kk * 8 + 2 * t];
                mma8(acc[0][nt], a[0], (uint32_t)bp, (uint32_t)(bp >> 32));
                mma8(acc[1][nt], a[1], (uint32_t)bp, (uint32_t)(bp >> 32));
            }
        }

        // epilogue
        #pragma unroll
        for (int mi = 0; mi < 2; ++mi) {
            #pragma unroll
            for (int nt = 0; nt < 8; ++nt) {
                int row = bm + wm * 32 + mi * 16 + g;
                int col = wn * 64 + nt * 8 + 2 * t;
                float v0 = acc[mi][nt][0], v1 = acc[mi][nt][1];
                float v2 = acc[mi][nt][2], v3 = acc[mi][nt][3];
                if (amode == 0) {
                    if (wi <= 1) {
                        // q/k: tf32 bits, slot-interleaved dims; k rows perm'd
                        int s0 = slot8(col);
                        int s1 = s0 + 2;
                        int r0 = (wi == 1) ? perm8(row) : row;
                        int r1 = (wi == 1) ? perm8(row + 8) : (row + 8);
                        float* base0 = g_qkvg + (size_t)r0 * 512 + wi * 128;
                        float* base1 = g_qkvg + (size_t)r1 * 512 + wi * 128;
                        base0[s0] = __uint_as_float(f2tf(v0));
                        base0[s1] = __uint_as_float(f2tf(v1));
                        base1[s0] = __uint_as_float(f2tf(v2));
                        base1[s1] = __uint_as_float(f2tf(v3));
                    } else if (wi == 2) {   // v: tf32, natural layout
                        float2 r0 = { __uint_as_float(f2tf(v0)), __uint_as_float(f2tf(v1)) };
                        float2 r1 = { __uint_as_float(f2tf(v2)), __uint_as_float(f2tf(v3)) };
                        *(float2*)(g_qkvg + (size_t)row * 512 + 256 + col) = r0;
                        *(float2*)(g_qkvg + (size_t)(row + 8) * 512 + 256 + col) = r1;
                    } else {                // g: + bias, fp32 natural
                        float2 bb = *(const float2*)(bias + col);
                        float2 r0 = { v0 + bb.x, v1 + bb.y };
                        float2 r1 = { v2 + bb.x, v3 + bb.y };
                        *(float2*)(g_qkvg + (size_t)row * 512 + 384 + col) = r0;
                        *(float2*)(g_qkvg + (size_t)(row + 8) * 512 + 384 + col) = r1;
                    }
                } else {
                    float2 bb = *(const float2*)(bias + col);
                    float2 r0 = { v0 + bb.x, v1 + bb.y };
                    float2 r1 = { v2 + bb.x, v3 + bb.y };
                    *(float2*)(Cext + (size_t)row * 128 + col) = r0;
                    *(float2*)(Cext + (size_t)(row + 8) * 128 + col) = r1;
                }
            }
        }
    }
}

// ---------------------------------------------------------------------------
// Kernel D: tf32 mma flash attention, fixed-max exp2 softmax.
// q-tile 128, 8 warps. K staged by straight copy (pre-permuted in gmem),
// V transposed in smem (conflict-free scatter), next-tile K/V prefetched
// into registers. Bias = tri (gmem, log2e-scaled, perm'd) + mask row (smem).
// ---------------------------------------------------------------------------
__global__ void __launch_bounds__(256) attn_mma() {
    __shared__ __align__(16) uint32_t Ks[64][40];  // stride 40: frag-conflict-free
    __shared__ __align__(16) uint32_t Vt[32][72];  // stride 72: frag-conflict-free
    __shared__ __align__(16) float mb[384];

    const int qt  = blockIdx.x;       // 0..2
    const int h   = blockIdx.y;       // 0..3
    const int i   = blockIdx.z;       // 0..383
    const int tid = threadIdx.x;
    const int w = tid >> 5, lane = tid & 31;
    const int g = lane >> 2, t = lane & 3;
    const int q0 = qt * 128;

    if (tid < 96)
        ((float4*)mb)[tid] = *(const float4*)(g_mb + (size_t)i * JDIM + tid * 4);

    // Q fragments: pre-scaled, tf32, slot-interleaved -> LDG.64 per k-chunk
    uint32_t qa[4][4];
    const int qr = q0 + w * 16 + g;
    {
        const float* p0 = g_qkvg + ((size_t)i * JDIM + qr) * 512 + h * HD;
        const float* p1 = p0 + 8 * 512;
        #pragma unroll
        for (int kk = 0; kk < 4; ++kk) {
            uint64_t u0 = *(const uint64_t*)(p0 + kk * 8 + 2 * t);
            uint64_t u1 = *(const uint64_t*)(p1 + kk * 8 + 2 * t);
            qa[kk][0] = (uint32_t)u0; qa[kk][2] = (uint32_t)(u0 >> 32);
            qa[kk][1] = (uint32_t)u1; qa[kk][3] = (uint32_t)(u1 >> 32);
        }
    }

    float l0 = 0.0f, l1 = 0.0f;
    float o[4][4];
    #pragma unroll
    for (int nt = 0; nt < 4; ++nt)
        #pragma unroll
        for (int j = 0; j < 4; ++j) o[nt][j] = 0.0f;

    // staging maps: K by (row=tid>>2, quarter=tid&3); V by (key=tid&63, quarter=tid>>6)
    const int ksr = tid >> 2, ksh = tid & 3;
    const int vr  = tid & 63, vsh = tid >> 6;
    const int vpr = perm8(vr);
    const float* trow0 = g_tri + (size_t)h * NPIX + (size_t)qr * JDIM;
    const float* trow1 = trow0 + 8 * JDIM;

    const float* kvrow = g_qkvg + ((size_t)i * JDIM) * 512;

    // prefetch tile 0
    float4 kf0, kf1, vf0, vf1;
    {
        const float4* kb = (const float4*)(kvrow + (size_t)ksr * 512 + 128 + h * HD + ksh * 8);
        kf0 = kb[0]; kf1 = kb[1];
        const float4* vb = (const float4*)(kvrow + (size_t)vr * 512 + 256 + h * HD + vsh * 8);
        vf0 = vb[0]; vf1 = vb[1];
    }

    for (int kt = 0; kt < 6; ++kt) {
        const int k0 = kt * 64;
        __syncthreads();   // smem free
        // store staged tile
        *(float4*)&Ks[ksr][ksh * 8]     = *(float4*)&kf0;
        *(float4*)&Ks[ksr][ksh * 8 + 4] = *(float4*)&kf1;
        {
            int d0 = vsh * 8;
            Vt[d0 + 0][vpr] = __float_as_uint(vf0.x);
            Vt[d0 + 1][vpr] = __float_as_uint(vf0.y);
            Vt[d0 + 2][vpr] = __float_as_uint(vf0.z);
            Vt[d0 + 3][vpr] = __float_as_uint(vf0.w);
            Vt[d0 + 4][vpr] = __float_as_uint(vf1.x);
            Vt[d0 + 5][vpr] = __float_as_uint(vf1.y);
            Vt[d0 + 6][vpr] = __float_as_uint(vf1.z);
            Vt[d0 + 7][vpr] = __float_as_uint(vf1.w);
        }

        // S init from tri (gmem; overlaps barrier)
        float s[8][4];
        #pragma unroll
        for (int nt = 0; nt < 8; ++nt) {
            float2 a = *(const float2*)(trow0 + k0 + nt * 8 + 2 * t);
            float2 b = *(const float2*)(trow1 + k0 + nt * 8 + 2 * t);
            s[nt][0] = a.x; s[nt][1] = a.y; s[nt][2] = b.x; s[nt][3] = b.y;
        }
        __syncthreads();   // smem ready

        // prefetch next tile (in flight during compute)
        if (kt < 5) {
            const float4* kb = (const float4*)(kvrow + (size_t)(k0 + 64 + ksr) * 512 + 128 + h * HD + ksh * 8);
            kf0 = kb[0]; kf1 = kb[1];
            const float4* vb = (const float4*)(kvrow + (size_t)(k0 + 64 + vr) * 512 + 256 + h * HD + vsh * 8);
            vf0 = vb[0]; vf1 = vb[1];
        }

        // + mask bias, S += Q K^T
        #pragma unroll
        for (int nt = 0; nt < 8; ++nt) {
            float2 mv = *(const float2*)&mb[k0 + nt * 8 + 2 * t];
            s[nt][0] += mv.x; s[nt][1] += mv.y;
            s[nt][2] += mv.x; s[nt][3] += mv.y;
            #pragma unroll
            for (int kk = 0; kk < 4; ++kk) {
                uint64_t bp = *(const uint64_t*)&Ks[nt * 8 + g][kk * 8 + 2 * t];
                mma8(s[nt], qa[kk], (uint32_t)bp, (uint32_t)(bp >> 32));
            }
        }

        // fixed-max exp2 softmax weights + partial row sums
        #pragma unroll
        for (int nt = 0; nt < 8; ++nt) {
            s[nt][0] = ex2(fmaxf(s[nt][0], -100.f));
            s[nt][1] = ex2(fmaxf(s[nt][1], -100.f));
            s[nt][2] = ex2(fmaxf(s[nt][2], -100.f));
            s[nt][3] = ex2(fmaxf(s[nt][3], -100.f));
            l0 += s[nt][0] + s[nt][1];
            l1 += s[nt][2] + s[nt][3];
        }

        // O += P V
        #pragma unroll
        for (int kk = 0; kk < 8; ++kk) {
            uint32_t pa[4];
            pa[0] = f2tf(s[kk][0]);
            pa[1] = f2tf(s[kk][2]);
            pa[2] = f2tf(s[kk][1]);
            pa[3] = f2tf(s[kk][3]);
            #pragma unroll
            for (int nt = 0; nt < 4; ++nt) {
                uint64_t bp = *(const uint64_t*)&Vt[nt * 8 + g][kk * 8 + 2 * t];
                mma8(o[nt], pa, (uint32_t)bp, (uint32_t)(bp >> 32));
            }
        }
    }

    // final l reduction (once, not per tile)
    l0 += __shfl_xor_sync(0xffffffffu, l0, 1);
    l0 += __shfl_xor_sync(0xffffffffu, l0, 2);
    l1 += __shfl_xor_sync(0xffffffffu, l1, 1);
    l1 += __shfl_xor_sync(0xffffffffu, l1, 2);
    float inv0 = 1.0f / l0, inv1 = 1.0f / l1;

    // epilogue: normalize, gate, store slot-interleaved tf32 to g_og
    size_t pix0 = (size_t)i * JDIM + qr;
    size_t pix1 = pix0 + 8;
    const float* gt0 = g_qkvg + pix0 * 512 + 384 + h * HD;
    const float* gt1 = g_qkvg + pix1 * 512 + 384 + h * HD;
    float* o0 = g_og + pix0 * CH + h * HD;
    float* o1 = g_og + pix1 * CH + h * HD;
    #pragma unroll
    for (int nt = 0; nt < 4; ++nt) {
        int d = nt * 8 + 2 * t;
        int s0 = slot8(d), s1 = s0 + 2;
        float2 gv0 = *(const float2*)(gt0 + d);
        float2 gv1 = *(const float2*)(gt1 + d);
        o0[s0] = __uint_as_float(f2tf(o[nt][0] * inv0 * (1.0f / (1.0f + __expf(-gv0.x)))));
        o0[s1] = __uint_as_float(f2tf(o[nt][1] * inv0 * (1.0f / (1.0f + __expf(-gv0.y)))));
        o1[s0] = __uint_as_float(f2tf(o[nt][2] * inv1 * (1.0f / (1.0f + __expf(-gv1.x)))));
        o1[s1] = __uint_as_float(f2tf(o[nt][3] * inv1 * (1.0f / (1.0f + __expf(-gv1.y)))));
    }
}

// ---------------------------------------------------------------------------
// Launch.  Inputs: x, mask, ln_w, ln_b, w_tri, wq, wk, wv, wg, bg, wo, bo
// ---------------------------------------------------------------------------
extern "C" void kernel_launch(void* const* d_in, const int* in_sizes, int n_in,
                              void* d_out, int out_size) {
    const float* x     = (const float*)d_in[0];
    const float* mask  = (const float*)d_in[1];
    const float* ln_w  = (const float*)d_in[2];
    const float* ln_b  = (const float*)d_in[3];
    const float* w_tri = (const float*)d_in[4];
    const float* wq    = (const float*)d_in[5];
    const float* wk    = (const float*)d_in[6];
    const float* wv    = (const float*)d_in[7];
    const float* wg    = (const float*)d_in[8];
    const float* bg    = (const float*)d_in[9];
    const float* wo    = (const float*)d_in[10];
    const float* bo    = (const float*)d_in[11];
    float* out = (float*)d_out;

    static bool attr_done = false;
    if (!attr_done) {
        cudaFuncSetAttribute(proj_kernel,
                             cudaFuncAttributeMaxDynamicSharedMemorySize,
                             (int)SMEM_PROJ);
        attr_done = true;
    }

    prepw_kernel<<<5, 128>>>(wq, wk, wv, wg, wo);
    maskb_kernel<<<(NPIX + 255) / 256, 256>>>(mask);

    // fused LN + tri + q,k,v,g projections
    proj_kernel<<<NPIX / 256, 512, SMEM_PROJ>>>(0, 4, bg, 3,
                                                x, ln_w, ln_b, w_tri,
                                                nullptr, 0);

    // attention (tri + mask bias, gating fused)
    attn_mma<<<dim3(3, NH, IDIM), 256>>>();

    // output projection
    proj_kernel<<<NPIX / 256, 512, SMEM_PROJ>>>(4, 1, bo, 0,
                                                nullptr, nullptr, nullptr, nullptr,
                                                out, 1);
}

// round 5
// speedup vs baseline: 2.9225x; 1.1031x over previous
#include <cuda_runtime.h>
#include <cstdint>

constexpr int IDIM = 384;
constexpr int JDIM = 384;
constexpr int NPIX = IDIM * JDIM;      // 147456
constexpr int CH   = 128;
constexpr int NH   = 4;
constexpr int HD   = 32;
constexpr float LN_EPS = 1e-5f;
constexpr float QSCALE = 0.17677669529663687f;  // 1/sqrt(32)
constexpr float LOG2E  = 1.4426950408889634f;

// Static device scratch
__device__ float g_qkvg[(size_t)NPIX * 512];   // q|k|-|g (q,k tf32 bits, slot-interleaved; k rows perm'd; q pre-scaled)
__device__ float g_vt[(size_t)IDIM * NH * HD * JDIM];  // V transposed: [i][h][d][perm8(j)], tf32 bits
__device__ float g_tri[(size_t)NH * NPIX];     // tri bias * log2e, k-index perm'd
__device__ float g_mb[(size_t)NPIX];           // 1e9*log2e*(mask-1), k-index perm'd
__device__ float g_og[(size_t)NPIX * CH];      // gated attn out, slot-interleaved, tf32 bits
__device__ uint32_t g_wt[5][128][128];         // transposed tf32 weights, k pair-perm'd

// ---------------------------------------------------------------------------
__device__ __forceinline__ uint32_t f2tf(float f) {
    uint32_t u;
    asm("cvt.rna.tf32.f32 %0, %1;" : "=r"(u) : "f"(f));
    return u;
}
__device__ __forceinline__ float ex2(float x) {
    float y;
    asm("ex2.approx.f32 %0, %1;" : "=f"(y) : "f"(x));
    return y;
}
__device__ __forceinline__ void mma8(float* d, const uint32_t* a,
                                     uint32_t b0, uint32_t b1) {
    asm volatile(
        "mma.sync.aligned.m16n8k8.row.col.f32.tf32.tf32.f32 "
        "{%0,%1,%2,%3}, {%4,%5,%6,%7}, {%8,%9}, {%0,%1,%2,%3};\n"
        : "+f"(d[0]), "+f"(d[1]), "+f"(d[2]), "+f"(d[3])
        : "r"(a[0]), "r"(a[1]), "r"(a[2]), "r"(a[3]), "r"(b0), "r"(b1));
}
__device__ __forceinline__ void cpa16(void* dst, const void* src) {
    unsigned d = (unsigned)__cvta_generic_to_shared(dst);
    asm volatile("cp.async.cg.shared.global [%0], [%1], 16;\n"
                 :: "r"(d), "l"(src));
}
// rotate-left-1 within 3 bits: write position for key/row index
__device__ __forceinline__ int perm8(int x) {
    return (x & ~7) | (((x & 3) << 1) | ((x >> 2) & 1));
}
// slot interleave within groups of 8: dim d<4 -> 2d, else 2(d-4)+1
__device__ __forceinline__ int slot8(int x) {
    int w = x & 7;
    return (x & ~7) | ((w < 4) ? (2 * w) : (2 * (w - 4) + 1));
}

// ---------------------------------------------------------------------------
// Kernel A: one-shot weight prep (transpose + tf32 + k pair-perm + q scale)
// ---------------------------------------------------------------------------
__global__ void prepw_kernel(const float* __restrict__ wq,
                             const float* __restrict__ wk,
                             const float* __restrict__ wv,
                             const float* __restrict__ wg,
                             const float* __restrict__ wo) {
    const float* Ws[5] = { wq, wk, wv, wg, wo };
    int wi = blockIdx.x;
    int k  = threadIdx.x;
    float scale = (wi == 0) ? (QSCALE * LOG2E) : 1.0f;
    const float4* src = (const float4*)(Ws[wi] + (size_t)k * 128);
    int pk = perm8(k);
    #pragma unroll
    for (int c = 0; c < 32; ++c) {
        float4 v = src[c];
        g_wt[wi][c * 4 + 0][pk] = f2tf(v.x * scale);
        g_wt[wi][c * 4 + 1][pk] = f2tf(v.y * scale);
        g_wt[wi][c * 4 + 2][pk] = f2tf(v.z * scale);
        g_wt[wi][c * 4 + 3][pk] = f2tf(v.w * scale);
    }
}

// ---------------------------------------------------------------------------
// Kernel B: permuted, log2e-scaled mask-bias rows
// ---------------------------------------------------------------------------
__global__ void maskb_kernel(const float* __restrict__ mask) {
    int idx = blockIdx.x * 256 + threadIdx.x;
    if (idx >= NPIX) return;
    int i = idx / JDIM;
    int j = idx - i * JDIM;
    g_mb[(size_t)i * JDIM + perm8(j)] = (1e9f * LOG2E) * (mask[idx] - 1.0f);
}

// ---------------------------------------------------------------------------
// Kernel C: fused {LayerNorm + tri-proj} + tf32 mma projections.
// ---------------------------------------------------------------------------
constexpr int PPAD = 136;
constexpr size_t SMEM_PROJ = (size_t)(256 * PPAD + 128 * PPAD + 768) * 4;

__global__ void __launch_bounds__(512) proj_kernel(
        int wbase, int nw, const float* __restrict__ bias, int bias_wi,
        const float* __restrict__ X,
        const float* __restrict__ ln_w, const float* __restrict__ ln_b,
        const float* __restrict__ w_tri,
        float* __restrict__ Cext, int amode) {
    extern __shared__ uint32_t smu[];
    uint32_t* Asu = smu;                    // [256][PPAD]
    uint32_t* Wtu = smu + 256 * PPAD;       // [128][PPAD]
    float* lnw  = (float*)(Wtu + 128 * PPAD);
    float* lnb  = lnw + 128;
    float* wtri = lnb + 128;

    const int tid = threadIdx.x;
    const int bm  = blockIdx.x * 256;

    if (amode == 0) {
        if (tid < 32)        ((float4*)lnw)[tid]       = ((const float4*)ln_w)[tid];
        else if (tid < 64)   ((float4*)lnb)[tid - 32]  = ((const float4*)ln_b)[tid - 32];
        else if (tid < 192)  ((float4*)wtri)[tid - 64] = ((const float4*)w_tri)[tid - 64];
    }
    __syncthreads();

    // ---- stage A ----
    {
        int r = tid >> 1, half = tid & 1;
        int gw = bm + r;
        uint32_t* arow = Asu + r * PPAD;

        if (amode == 0) {
            const float4* xr = (const float4*)(X + (size_t)gw * 128 + half * 64);
            float s = 0.f, ss = 0.f;
            #pragma unroll
            for (int c = 0; c < 16; ++c) {
                float4 v = xr[c];
                s  += v.x + v.y + v.z + v.w;
                ss += v.x * v.x + v.y * v.y + v.z * v.z + v.w * v.w;
            }
            s  += __shfl_xor_sync(0xffffffffu, s, 1);
            ss += __shfl_xor_sync(0xffffffffu, ss, 1);
            float mu = s * (1.0f / 128.0f);
            float rs = rsqrtf(fmaxf(ss * (1.0f / 128.0f) - mu * mu, 0.f) + LN_EPS);

            float th0 = 0.f, th1 = 0.f, th2 = 0.f, th3 = 0.f;
            #pragma unroll
            for (int c = 0; c < 16; ++c) {
                float4 v = xr[c];
                float vs[4] = { v.x, v.y, v.z, v.w };
                #pragma unroll
                for (int e = 0; e < 4; ++e) {
                    int ch = half * 64 + c * 4 + e;
                    float xn = (vs[e] - mu) * rs * lnw[ch] + lnb[ch];
                    float4 wt = ((const float4*)wtri)[ch];
                    th0 += xn * wt.x; th1 += xn * wt.y;
                    th2 += xn * wt.z; th3 += xn * wt.w;
                    arow[perm8(ch)] = f2tf(xn);
                }
            }
            th0 += __shfl_xor_sync(0xffffffffu, th0, 1);
            th1 += __shfl_xor_sync(0xffffffffu, th1, 1);
            th2 += __shfl_xor_sync(0xffffffffu, th2, 1);
            th3 += __shfl_xor_sync(0xffffffffu, th3, 1);
            if (half == 0) {
                size_t dst = (size_t)perm8(gw);
                g_tri[0 * (size_t)NPIX + dst] = th0 * LOG2E;
                g_tri[1 * (size_t)NPIX + dst] = th1 * LOG2E;
                g_tri[2 * (size_t)NPIX + dst] = th2 * LOG2E;
                g_tri[3 * (size_t)NPIX + dst] = th3 * LOG2E;
            }
        } else {
            const float4* xr = (const float4*)(g_og + (size_t)gw * 128 + half * 64);
            #pragma unroll
            for (int c = 0; c < 16; ++c)
                *(float4*)(arow + half * 64 + c * 4) = xr[c];
        }
    }

    const int w = tid >> 5, lane = tid & 31;
    const int g = lane >> 2, t = lane & 3;
    const int wm = w >> 1, wn = w & 1;

    for (int wi = 0; wi < nw; ++wi) {
        __syncthreads();
        {
            int n = tid >> 2, q4 = tid & 3;
            const float4* src = (const float4*)&g_wt[wbase + wi][n][q4 * 32];
            uint32_t* dst = Wtu + n * PPAD + q4 * 32;
            #pragma unroll
            for (int c = 0; c < 8; ++c)
                *(float4*)(dst + c * 4) = src[c];
        }
        __syncthreads();

        float acc[2][8][4];
        #pragma unroll
        for (int mi = 0; mi < 2; ++mi)
            #pragma unroll
            for (int nt = 0; nt < 8; ++nt)
                #pragma unroll
                for (int j = 0; j < 4; ++j) acc[mi][nt][j] = 0.0f;

        #pragma unroll
        for (int kk = 0; kk < 16; ++kk) {
            uint32_t a[2][4];
            #pragma unroll
            for (int mi = 0; mi < 2; ++mi) {
                int rb = wm * 32 + mi * 16;
                uint64_t p0 = *(const uint64_t*)&Asu[(rb + g) * PPAD + kk * 8 + 2 * t];
                uint64_t p1 = *(const uint64_t*)&Asu[(rb + g + 8) * PPAD + kk * 8 + 2 * t];
                a[mi][0] = (uint32_t)p0; a[mi][2] = (uint32_t)(p0 >> 32);
                a[mi][1] = (uint32_t)p1; a[mi][3] = (uint32_t)(p1 >> 32);
            }
            #pragma unroll
            for (int nt = 0; nt < 8; ++nt) {
                uint64_t bp = *(const uint64_t*)&Wtu[(wn * 64 + nt * 8 + g) * PPAD + kk * 8 + 2 * t];
                mma8(acc[0][nt], a[0], (uint32_t)bp, (uint32_t)(bp >> 32));
                mma8(acc[1][nt], a[1], (uint32_t)bp, (uint32_t)(bp >> 32));
            }
        }

        // epilogue
        #pragma unroll
        for (int mi = 0; mi < 2; ++mi) {
            int row0 = bm + wm * 32 + mi * 16 + g;
            int row1 = row0 + 8;
            // pixel coords for V scatter
            int i0 = row0 / JDIM, j0 = row0 - i0 * JDIM;
            int i1 = row1 / JDIM, j1 = row1 - i1 * JDIM;
            int pj0 = perm8(j0), pj1 = perm8(j1);
            #pragma unroll
            for (int nt = 0; nt < 8; ++nt) {
                int col = wn * 64 + nt * 8 + 2 * t;
                float v0 = acc[mi][nt][0], v1 = acc[mi][nt][1];
                float v2 = acc[mi][nt][2], v3 = acc[mi][nt][3];
                if (amode == 0) {
                    if (wi <= 1) {          // q/k: tf32, slot-interleaved; k rows perm'd
                        int s0 = slot8(col), s1 = s0 + 2;
                        int r0 = (wi == 1) ? perm8(row0) : row0;
                        int r1 = (wi == 1) ? perm8(row1) : row1;
                        float* base0 = g_qkvg + (size_t)r0 * 512 + wi * 128;
                        float* base1 = g_qkvg + (size_t)r1 * 512 + wi * 128;
                        base0[s0] = __uint_as_float(f2tf(v0));
                        base0[s1] = __uint_as_float(f2tf(v1));
                        base1[s0] = __uint_as_float(f2tf(v2));
                        base1[s1] = __uint_as_float(f2tf(v3));
                    } else if (wi == 2) {   // v: transposed tf32 into g_vt
                        int hh = col >> 5, d0 = col & 31;
                        size_t b0 = ((size_t)(i0 * NH + hh) * HD + d0) * JDIM;
                        size_t b1 = ((size_t)(i1 * NH + hh) * HD + d0) * JDIM;
                        g_vt[b0 + pj0]        = __uint_as_float(f2tf(v0));
                        g_vt[b0 + JDIM + pj0] = __uint_as_float(f2tf(v1));
                        g_vt[b1 + pj1]        = __uint_as_float(f2tf(v2));
                        g_vt[b1 + JDIM + pj1] = __uint_as_float(f2tf(v3));
                    } else {                // g: + bias, fp32 natural
                        float2 bb = *(const float2*)(bias + col);
                        float2 r0 = { v0 + bb.x, v1 + bb.y };
                        float2 r1 = { v2 + bb.x, v3 + bb.y };
                        *(float2*)(g_qkvg + (size_t)row0 * 512 + 384 + col) = r0;
                        *(float2*)(g_qkvg + (size_t)row1 * 512 + 384 + col) = r1;
                    }
                } else {
                    float2 bb = *(const float2*)(bias + col);
                    float2 r0 = { v0 + bb.x, v1 + bb.y };
                    float2 r1 = { v2 + bb.x, v3 + bb.y };
                    *(float2*)(Cext + (size_t)row0 * 128 + col) = r0;
                    *(float2*)(Cext + (size_t)row1 * 128 + col) = r1;
                }
            }
        }
    }
}

// ---------------------------------------------------------------------------
// Kernel D: tf32 mma flash attention. 192 threads, 6 warps x 32 q-rows,
// q-tile 192. cp.async double-buffered K/V staging (both copy-ready in gmem).
// Each K/V b-fragment feeds 2 MMAs (two m-blocks per warp).
// ---------------------------------------------------------------------------
__global__ void __launch_bounds__(192, 2) attn_mma() {
    __shared__ __align__(16) uint32_t Ks[2][64][40];
    __shared__ __align__(16) uint32_t Vt[2][32][72];
    __shared__ __align__(16) float mb[384];

    const int qt  = blockIdx.x;       // 0..1
    const int h   = blockIdx.y;       // 0..3
    const int i   = blockIdx.z;       // 0..383
    const int tid = threadIdx.x;
    const int w = tid >> 5, lane = tid & 31;
    const int g = lane >> 2, t = lane & 3;
    const int q0 = qt * 192;

    if (tid < 96)
        ((float4*)mb)[tid] = *(const float4*)(g_mb + (size_t)i * JDIM + tid * 4);

    // Q fragments: 2 m-blocks of 16 rows
    uint32_t qa[2][4][4];
    #pragma unroll
    for (int mi = 0; mi < 2; ++mi) {
        int qr = q0 + w * 32 + mi * 16 + g;
        const float* p0 = g_qkvg + ((size_t)i * JDIM + qr) * 512 + h * HD;
        const float* p1 = p0 + 8 * 512;
        #pragma unroll
        for (int kk = 0; kk < 4; ++kk) {
            uint64_t u0 = *(const uint64_t*)(p0 + kk * 8 + 2 * t);
            uint64_t u1 = *(const uint64_t*)(p1 + kk * 8 + 2 * t);
            qa[mi][kk][0] = (uint32_t)u0; qa[mi][kk][2] = (uint32_t)(u0 >> 32);
            qa[mi][kk][1] = (uint32_t)u1; qa[mi][kk][3] = (uint32_t)(u1 >> 32);
        }
    }

    const float* kbase = g_qkvg + ((size_t)i * JDIM) * 512 + 128 + h * HD;
    const float* vbase = g_vt + (size_t)(i * NH + h) * HD * JDIM;

    // stage tile k0 into buffer st
    auto stage = [&](int st, int k0) {
        #pragma unroll
        for (int c = tid; c < 1024; c += 192) {
            if (c < 512) {
                int r = c >> 3, seg = c & 7;
                cpa16(&Ks[st][r][seg * 4],
                      kbase + (size_t)(k0 + r) * 512 + seg * 4);
            } else {
                int vc = c - 512;
                int d = vc >> 4, seg = vc & 15;
                cpa16(&Vt[st][d][seg * 4],
                      vbase + (size_t)d * JDIM + k0 + seg * 4);
            }
        }
        asm volatile("cp.async.commit_group;\n");
    };

    stage(0, 0);

    float l[2][2] = { {0.f, 0.f}, {0.f, 0.f} };
    float o[2][4][4];
    #pragma unroll
    for (int mi = 0; mi < 2; ++mi)
        #pragma unroll
        for (int nt = 0; nt < 4; ++nt)
            #pragma unroll
            for (int j = 0; j < 4; ++j) o[mi][nt][j] = 0.0f;

    const float* tb = g_tri + (size_t)h * NPIX;

    for (int kt = 0; kt < 6; ++kt) {
        const int k0 = kt * 64;
        const int st = kt & 1;

        // S init from tri (gmem LDG, independent of smem)
        float s[2][8][4];
        #pragma unroll
        for (int mi = 0; mi < 2; ++mi) {
            const float* t0 = tb + (size_t)(q0 + w * 32 + mi * 16 + g) * JDIM + k0;
            const float* t1 = t0 + 8 * JDIM;
            #pragma unroll
            for (int nt = 0; nt < 8; ++nt) {
                float2 a = *(const float2*)(t0 + nt * 8 + 2 * t);
                float2 b = *(const float2*)(t1 + nt * 8 + 2 * t);
                s[mi][nt][0] = a.x; s[mi][nt][1] = a.y;
                s[mi][nt][2] = b.x; s[mi][nt][3] = b.y;
            }
        }

        asm volatile("cp.async.wait_group 0;\n");
        __syncthreads();
        if (kt < 5) stage(st ^ 1, k0 + 64);

        // + mask bias, S += Q K^T (each b-frag feeds 2 m-blocks)
        #pragma unroll
        for (int nt = 0; nt < 8; ++nt) {
            float2 mv = *(const float2*)&mb[k0 + nt * 8 + 2 * t];
            #pragma unroll
            for (int mi = 0; mi < 2; ++mi) {
                s[mi][nt][0] += mv.x; s[mi][nt][1] += mv.y;
                s[mi][nt][2] += mv.x; s[mi][nt][3] += mv.y;
            }
            #pragma unroll
            for (int kk = 0; kk < 4; ++kk) {
                uint64_t bp = *(const uint64_t*)&Ks[st][nt * 8 + g][kk * 8 + 2 * t];
                mma8(s[0][nt], qa[0][kk], (uint32_t)bp, (uint32_t)(bp >> 32));
                mma8(s[1][nt], qa[1][kk], (uint32_t)bp, (uint32_t)(bp >> 32));
            }
        }

        // fixed-max exp2 softmax weights + partial sums
        #pragma unroll
        for (int mi = 0; mi < 2; ++mi)
            #pragma unroll
            for (int nt = 0; nt < 8; ++nt) {
                s[mi][nt][0] = ex2(fmaxf(s[mi][nt][0], -100.f));
                s[mi][nt][1] = ex2(fmaxf(s[mi][nt][1], -100.f));
                s[mi][nt][2] = ex2(fmaxf(s[mi][nt][2], -100.f));
                s[mi][nt][3] = ex2(fmaxf(s[mi][nt][3], -100.f));
                l[mi][0] += s[mi][nt][0] + s[mi][nt][1];
                l[mi][1] += s[mi][nt][2] + s[mi][nt][3];
            }

        // O += P V (b-frag shared across m-blocks)
        #pragma unroll
        for (int kk = 0; kk < 8; ++kk) {
            uint32_t pa0[4], pa1[4];
            pa0[0] = f2tf(s[0][kk][0]); pa0[1] = f2tf(s[0][kk][2]);
            pa0[2] = f2tf(s[0][kk][1]); pa0[3] = f2tf(s[0][kk][3]);
            pa1[0] = f2tf(s[1][kk][0]); pa1[1] = f2tf(s[1][kk][2]);
            pa1[2] = f2tf(s[1][kk][1]); pa1[3] = f2tf(s[1][kk][3]);
            #pragma unroll
            for (int nt = 0; nt < 4; ++nt) {
                uint64_t bp = *(const uint64_t*)&Vt[st][nt * 8 + g][kk * 8 + 2 * t];
                mma8(o[0][nt], pa0, (uint32_t)bp, (uint32_t)(bp >> 32));
                mma8(o[1][nt], pa1, (uint32_t)bp, (uint32_t)(bp >> 32));
            }
        }
    }

    // epilogue: reduce l, normalize, gate, store slot-interleaved tf32
    #pragma unroll
    for (int mi = 0; mi < 2; ++mi) {
        float l0 = l[mi][0], l1 = l[mi][1];
        l0 += __shfl_xor_sync(0xffffffffu, l0, 1);
        l0 += __shfl_xor_sync(0xffffffffu, l0, 2);
        l1 += __shfl_xor_sync(0xffffffffu, l1, 1);
        l1 += __shfl_xor_sync(0xffffffffu, l1, 2);
        float inv0 = 1.0f / l0, inv1 = 1.0f / l1;

        int qr = q0 + w * 32 + mi * 16 + g;
        size_t pix0 = (size_t)i * JDIM + qr;
        size_t pix1 = pix0 + 8;
        const float* gt0 = g_qkvg + pix0 * 512 + 384 + h * HD;
        const float* gt1 = g_qkvg + pix1 * 512 + 384 + h * HD;
        float* o0 = g_og + pix0 * CH + h * HD;
        float* o1 = g_og + pix1 * CH + h * HD;
        #pragma unroll
        for (int nt = 0; nt < 4; ++nt) {
            int d = nt * 8 + 2 * t;
            int s0 = slot8(d), s1 = s0 + 2;
            float2 gv0 = *(const float2*)(gt0 + d);
            float2 gv1 = *(const float2*)(gt1 + d);
            o0[s0] = __uint_as_float(f2tf(o[mi][nt][0] * inv0 * (1.0f / (1.0f + __expf(-gv0.x)))));
            o0[s1] = __uint_as_float(f2tf(o[mi][nt][1] * inv0 * (1.0f / (1.0f + __expf(-gv0.y)))));
            o1[s0] = __uint_as_float(f2tf(o[mi][nt][2] * inv1 * (1.0f / (1.0f + __expf(-gv1.x)))));
            o1[s1] = __uint_as_float(f2tf(o[mi][nt][3] * inv1 * (1.0f / (1.0f + __expf(-gv1.y)))));
        }
    }
}

// ---------------------------------------------------------------------------
// Launch.  Inputs: x, mask, ln_w, ln_b, w_tri, wq, wk, wv, wg, bg, wo, bo
// ---------------------------------------------------------------------------
extern "C" void kernel_launch(void* const* d_in, const int* in_sizes, int n_in,
                              void* d_out, int out_size) {
    const float* x     = (const float*)d_in[0];
    const float* mask  = (const float*)d_in[1];
    const float* ln_w  = (const float*)d_in[2];
    const float* ln_b  = (const float*)d_in[3];
    const float* w_tri = (const float*)d_in[4];
    const float* bg    = (const float*)d_in[9];
    const float* bo    = (const float*)d_in[11];
    float* out = (float*)d_out;

    static bool attr_done = false;
    if (!attr_done) {
        cudaFuncSetAttribute(proj_kernel,
                             cudaFuncAttributeMaxDynamicSharedMemorySize,
                             (int)SMEM_PROJ);
        attr_done = true;
    }

    prepw_kernel<<<5, 128>>>((const float*)d_in[5], (const float*)d_in[6],
                             (const float*)d_in[7], (const float*)d_in[8],
                             (const float*)d_in[10]);
    maskb_kernel<<<(NPIX + 255) / 256, 256>>>(mask);

    // fused LN + tri + q,k,v,g projections
    proj_kernel<<<NPIX / 256, 512, SMEM_PROJ>>>(0, 4, bg, 3,
                                                x, ln_w, ln_b, w_tri,
                                                nullptr, 0);

    // attention (tri + mask bias, gating fused)
    attn_mma<<<dim3(2, NH, IDIM), 192>>>();

    // output projection
    proj_kernel<<<NPIX / 256, 512, SMEM_PROJ>>>(4, 1, bo, 0,
                                                nullptr, nullptr, nullptr, nullptr,
                                                out, 1);
}